// round 13
// baseline (speedup 1.0000x reference)
#include <cuda_runtime.h>
#include <cuda_fp16.h>
#include <cuda_bf16.h>
#include <stdint.h>
#include <math.h>

#define SEQ 2048
#define HID 2048
#define NH 16
#define QL 1536
#define KVL 512
#define DN 128
#define DR 64
#define DV 128
#define DQK 192
#define CKVW (KVL + DR)      // 576
#define FW (QL + CKVW)       // 2112
#define FWP 2176
#define QW (NH * DQK)        // 3072
#define KVW (NH * (DN + DV)) // 4096
#define AW (NH * DV)         // 2048

// ---------------- scratch ----------------
__device__ float  g_qc_s [(size_t)SEQ * FWP];
__device__ float  g_q_s  [(size_t)SEQ * QW];
__device__ __half g_hid_h[(size_t)SEQ * HID];
__device__ __half g_wf_h [(size_t)HID * FWP],  g_wf_l [(size_t)HID * FWP];
__device__ __half g_qb_h [(size_t)QL * QW],    g_qb_l [(size_t)QL * QW];
__device__ __half g_kvb_h[(size_t)KVL * KVW],  g_kvb_l[(size_t)KVL * KVW];
__device__ __half g_o_h  [(size_t)AW * HID],   g_o_l  [(size_t)AW * HID];
__device__ __half g_qan_h[(size_t)SEQ * QL];
__device__ __half g_ckn_h[(size_t)SEQ * KVL];
__device__ __half g_qs_h [(size_t)SEQ * QW],   g_qs_l [(size_t)SEQ * QW];
__device__ __half g_kv_h [(size_t)SEQ * KVW],  g_kv_l [(size_t)SEQ * KVW];
__device__ __half g_kpe_h[(size_t)SEQ * DR],   g_kpe_l[(size_t)SEQ * DR];
__device__ __half g_at_h [(size_t)SEQ * AW];

__device__ __forceinline__ uint32_t smem_u32(const void* p) {
    return (uint32_t)__cvta_generic_to_shared(p);
}

#define LDSM_X4(r0, r1, r2, r3, a)                                            \
    asm volatile("ldmatrix.sync.aligned.m8n8.x4.shared.b16 {%0,%1,%2,%3},[%4];" \
                 : "=r"(r0), "=r"(r1), "=r"(r2), "=r"(r3) : "r"(a))
#define LDSM_X2(r0, r1, a)                                                    \
    asm volatile("ldmatrix.sync.aligned.m8n8.x2.shared.b16 {%0,%1},[%2];"     \
                 : "=r"(r0), "=r"(r1) : "r"(a))
#define LDSM_X4_T(r0, r1, r2, r3, a)                                          \
    asm volatile("ldmatrix.sync.aligned.m8n8.x4.trans.shared.b16 {%0,%1,%2,%3},[%4];" \
                 : "=r"(r0), "=r"(r1), "=r"(r2), "=r"(r3) : "r"(a))

#define MMA16816(d, a0, a1, a2, a3, b0, b1)                                   \
    asm volatile("mma.sync.aligned.m16n8k16.row.col.f32.f16.f16.f32 "         \
                 "{%0,%1,%2,%3},{%4,%5,%6,%7},{%8,%9},{%0,%1,%2,%3};"          \
                 : "+f"(d[0]), "+f"(d[1]), "+f"(d[2]), "+f"(d[3])              \
                 : "r"(a0), "r"(a1), "r"(a2), "r"(a3), "r"(b0), "r"(b1))

#define CP_ASYNC16(dst, src)                                                  \
    asm volatile("cp.async.cg.shared.global [%0], [%1], 16;" :: "r"(dst), "l"(src))
#define CP_COMMIT() asm volatile("cp.async.commit_group;" ::: "memory")
#define CP_WAIT2()  asm volatile("cp.async.wait_group 2;" ::: "memory")
#define CP_WAIT1()  asm volatile("cp.async.wait_group 1;" ::: "memory")
#define CP_WAIT0()  asm volatile("cp.async.wait_group 0;" ::: "memory")

__device__ __forceinline__ void split_h2(float x, float y, uint32_t& h, uint32_t& l) {
    __half hx = __float2half_rn(x), hy = __float2half_rn(y);
    __half2 hp = __halves2half2(hx, hy);
    h = *(uint32_t*)&hp;
    __half2 lp = __halves2half2(__float2half_rn(x - __half2float(hx)),
                                __float2half_rn(y - __half2float(hy)));
    l = *(uint32_t*)&lp;
}

// ======== one prep kernel ========
#define NB1 8192
#define NB2 8704
#define NB3 9216
#define NB4 4096
#define NB5 8192
#define PREP_BLOCKS (NB1 + NB2 + NB3 + NB4 + NB5)

__global__ __launch_bounds__(256) void prep_kernel(
    const float* __restrict__ hidden,
    const float* __restrict__ wqa, const float* __restrict__ wkva,
    const float* __restrict__ wqb, const float* __restrict__ wkvb,
    const float* __restrict__ wo,
    __half* __restrict__ hidh,
    __half* __restrict__ wfh, __half* __restrict__ wfl,
    __half* __restrict__ qbh, __half* __restrict__ qbl,
    __half* __restrict__ kvbh, __half* __restrict__ kvbl,
    __half* __restrict__ oh, __half* __restrict__ ol)
{
    int b = blockIdx.x;
    if (b < NB1) {
        int i = b * 256 + threadIdx.x;
        float2 v = ((const float2*)hidden)[i];
        ((__half2*)hidh)[i] = __float22half2_rn(v);
    } else if (b < NB1 + NB2) {
        int i = (b - NB1) * 256 + threadIdx.x;
        int row = i / (FWP / 2), p = i % (FWP / 2);
        int col = 2 * p;
        float x = 0.f, y = 0.f;
        if (col < QL)      { x = wqa[(size_t)row * QL + col];         y = wqa[(size_t)row * QL + col + 1]; }
        else if (col < FW) { x = wkva[(size_t)row * CKVW + col - QL]; y = wkva[(size_t)row * CKVW + col - QL + 1]; }
        uint32_t hh, ll;
        split_h2(x, y, hh, ll);
        ((uint32_t*)wfh)[i] = hh;
        ((uint32_t*)wfl)[i] = ll;
    } else if (b < NB1 + NB2 + NB3) {
        int i = (b - NB1 - NB2) * 256 + threadIdx.x;
        float2 v = ((const float2*)wqb)[i];
        uint32_t hh, ll;
        split_h2(v.x, v.y, hh, ll);
        ((uint32_t*)qbh)[i] = hh;
        ((uint32_t*)qbl)[i] = ll;
    } else if (b < NB1 + NB2 + NB3 + NB4) {
        int i = (b - NB1 - NB2 - NB3) * 256 + threadIdx.x;
        float2 v = ((const float2*)wkvb)[i];
        uint32_t hh, ll;
        split_h2(v.x, v.y, hh, ll);
        ((uint32_t*)kvbh)[i] = hh;
        ((uint32_t*)kvbl)[i] = ll;
    } else {
        int i = (b - NB1 - NB2 - NB3 - NB4) * 256 + threadIdx.x;
        float2 v = ((const float2*)wo)[i];
        uint32_t hh, ll;
        split_h2(v.x, v.y, hh, ll);
        ((uint32_t*)oh)[i] = hh;
        ((uint32_t*)ol)[i] = ll;
    }
}

// ---------------- both RMSNorms ----------------
__global__ __launch_bounds__(256) void rmsnorm2_kernel(
    const float* __restrict__ qc, const float* __restrict__ gqa,
    const float* __restrict__ gkva, __half* __restrict__ qanh,
    __half* __restrict__ cknh)
{
    __shared__ float red[256];
    const float* p = qc + (size_t)blockIdx.x * FWP;
    float s = 0.f;
    for (int i = threadIdx.x; i < QL; i += 256) { float v = p[i]; s += v * v; }
    red[threadIdx.x] = s;
    __syncthreads();
#pragma unroll
    for (int off = 128; off > 0; off >>= 1) {
        if (threadIdx.x < off) red[threadIdx.x] += red[threadIdx.x + off];
        __syncthreads();
    }
    float inv = rsqrtf(red[0] / (float)QL + 1e-6f);
    for (int i = threadIdx.x; i < QL / 2; i += 256) {
        float v0 = p[2 * i] * inv * gqa[2 * i];
        float v1 = p[2 * i + 1] * inv * gqa[2 * i + 1];
        ((__half2*)qanh)[(size_t)blockIdx.x * (QL / 2) + i] = __float22half2_rn(make_float2(v0, v1));
    }
    __syncthreads();
    const float* p2 = p + QL;
    s = 0.f;
    for (int i = threadIdx.x; i < KVL; i += 256) { float v = p2[i]; s += v * v; }
    red[threadIdx.x] = s;
    __syncthreads();
#pragma unroll
    for (int off = 128; off > 0; off >>= 1) {
        if (threadIdx.x < off) red[threadIdx.x] += red[threadIdx.x + off];
        __syncthreads();
    }
    inv = rsqrtf(red[0] / (float)KVL + 1e-6f);
    for (int i = threadIdx.x; i < KVL / 2; i += 256) {
        float v0 = p2[2 * i] * inv * gkva[2 * i];
        float v1 = p2[2 * i + 1] * inv * gkva[2 * i + 1];
        ((__half2*)cknh)[(size_t)blockIdx.x * (KVL / 2) + i] = __float22half2_rn(make_float2(v0, v1));
    }
}

// ======== fp16x2 GEMM core: 4-stage K32 ring, 1 sync/iter, 2 CTAs/SM ========
// A stage: 128 rows x 64B (swizzle chunk ^= (r>>1)&3 -> conflict free at 64B pitch)
// B stage: 32 rows x 256B, h + l (swizzle chunk ^= r&7)
#define G4_A 8192
#define G4_B 8192
#define G4_STAGE (G4_A + 2 * G4_B)       // 24576
#define GEMM_SMEM_BYTES (4 * G4_STAGE)   // 98304

__device__ __forceinline__ void gemm_core(
    const __half* __restrict__ Ah, int lda,
    const __half* __restrict__ Bh, const __half* __restrict__ Bl, int ldb,
    float* __restrict__ C, __half* __restrict__ Ch, __half* __restrict__ Cl,
    int ldc, int N, int K, int row0, int col0, bool split_out, char* sm)
{
    const uint32_t sbase = smem_u32(sm);
    const int tid  = threadIdx.x;
    const int lane = tid & 31, w = tid >> 5;
    const int wm = w & 3, wn = w >> 2;

    float acc[2][8][4];
#pragma unroll
    for (int mt = 0; mt < 2; ++mt)
#pragma unroll
        for (int nt = 0; nt < 8; ++nt)
#pragma unroll
            for (int i = 0; i < 4; ++i) acc[mt][nt][i] = 0.f;

    auto do_cp = [&](int stage, int k0) {
        uint32_t sb = sbase + stage * G4_STAGE;
#pragma unroll
        for (int i = 0; i < 2; ++i) {        // A: 512 16B chunks
            int idx = i * 256 + tid;
            int r = idx >> 2, u = idx & 3;
            uint32_t off = r * 64 + ((u ^ ((r >> 1) & 3)) << 4);
            CP_ASYNC16(sb + off, Ah + (size_t)(row0 + r) * lda + k0 + u * 8);
        }
#pragma unroll
        for (int i = 0; i < 2; ++i) {        // B: 512 chunks per half-tile
            int idx = i * 256 + tid;
            int r = idx >> 4, u = idx & 15;
            uint32_t off = G4_A + r * 256 + ((u ^ (r & 7)) << 4);
            CP_ASYNC16(sb + off, Bh + (size_t)(k0 + r) * ldb + col0 + u * 8);
            CP_ASYNC16(sb + G4_B + off, Bl + (size_t)(k0 + r) * ldb + col0 + u * 8);
        }
    };

    const int nIter = K >> 5;                 // K-step 32
#pragma unroll
    for (int s = 0; s < 3; ++s) {
        if (s < nIter) do_cp(s, s << 5);
        CP_COMMIT();
    }

    for (int it = 0; it < nIter; ++it) {
        CP_WAIT2();                           // group(it) complete
        __syncthreads();                      // stage (it+3)&3 now free
        if (it + 3 < nIter) do_cp((it + 3) & 3, (it + 3) << 5);
        CP_COMMIT();

        char* base = sm + (it & 3) * G4_STAGE;
#pragma unroll
        for (int kg = 0; kg < 2; ++kg) {
            uint32_t ah[2][4];
#pragma unroll
            for (int mt = 0; mt < 2; ++mt) {
                int row = wm * 32 + mt * 16 + (lane & 15);
                int kc = kg * 2 + (lane >> 4);
                uint32_t ad = smem_u32(base + row * 64 + ((kc ^ ((row >> 1) & 3)) << 4));
                LDSM_X4(ah[mt][0], ah[mt][1], ah[mt][2], ah[mt][3], ad);
            }
            uint32_t bh[8][2], bl[8][2];
#pragma unroll
            for (int pr = 0; pr < 4; ++pr) {
                int k = kg * 16 + (lane & 15);
                int nc = wn * 8 + pr * 2 + (lane >> 4);
                uint32_t bd = smem_u32(base + G4_A + k * 256 + ((nc ^ (k & 7)) << 4));
                uint32_t t0, t1, t2, t3;
                LDSM_X4_T(t0, t1, t2, t3, bd);
                bh[2 * pr][0] = t0; bh[2 * pr][1] = t1;
                bh[2 * pr + 1][0] = t2; bh[2 * pr + 1][1] = t3;
                LDSM_X4_T(t0, t1, t2, t3, bd + G4_B);
                bl[2 * pr][0] = t0; bl[2 * pr][1] = t1;
                bl[2 * pr + 1][0] = t2; bl[2 * pr + 1][1] = t3;
            }
#pragma unroll
            for (int mt = 0; mt < 2; ++mt)
#pragma unroll
                for (int nt = 0; nt < 8; ++nt) {
                    MMA16816(acc[mt][nt], ah[mt][0], ah[mt][1], ah[mt][2], ah[mt][3],
                             bl[nt][0], bl[nt][1]);
                    MMA16816(acc[mt][nt], ah[mt][0], ah[mt][1], ah[mt][2], ah[mt][3],
                             bh[nt][0], bh[nt][1]);
                }
        }
    }

    const int g = lane >> 2, t = lane & 3;
#pragma unroll
    for (int mt = 0; mt < 2; ++mt) {
        int r = row0 + wm * 32 + mt * 16 + g;
#pragma unroll
        for (int nt = 0; nt < 8; ++nt) {
            int c = col0 + wn * 64 + nt * 8 + 2 * t;
            if (split_out) {
                uint32_t hh, ll;
                split_h2(acc[mt][nt][0], acc[mt][nt][1], hh, ll);
                *(uint32_t*)(Ch + (size_t)r * ldc + c) = hh;
                *(uint32_t*)(Cl + (size_t)r * ldc + c) = ll;
                split_h2(acc[mt][nt][2], acc[mt][nt][3], hh, ll);
                *(uint32_t*)(Ch + (size_t)(r + 8) * ldc + c) = hh;
                *(uint32_t*)(Cl + (size_t)(r + 8) * ldc + c) = ll;
            } else if (c < N) {
                *(float2*)(C + (size_t)r * ldc + c)       = make_float2(acc[mt][nt][0], acc[mt][nt][1]);
                *(float2*)(C + (size_t)(r + 8) * ldc + c) = make_float2(acc[mt][nt][2], acc[mt][nt][3]);
            }
        }
    }
}

__global__ __launch_bounds__(256, 2) void gemm_f32out(
    const __half* __restrict__ Ah, int lda,
    const __half* __restrict__ Bh, const __half* __restrict__ Bl, int ldb,
    float* __restrict__ C, int ldc, int N, int K)
{
    extern __shared__ char sm[];
    gemm_core(Ah, lda, Bh, Bl, ldb, C, (__half*)0, (__half*)0, ldc, N, K,
              blockIdx.y * 128, blockIdx.x * 128, false, sm);
}

#define G2_TILES 384
#define G3_TILES 512
__global__ __launch_bounds__(256, 2) void gemm_dual(
    const __half* __restrict__ A2, const __half* __restrict__ B2h,
    const __half* __restrict__ B2l, float* __restrict__ C2,
    const __half* __restrict__ A3, const __half* __restrict__ B3h,
    const __half* __restrict__ B3l, __half* __restrict__ C3h, __half* __restrict__ C3l)
{
    extern __shared__ char sm[];
    int b = blockIdx.x;
    if (b < G2_TILES) {
        gemm_core(A2, QL, B2h, B2l, QW, C2, (__half*)0, (__half*)0, QW, QW, QL,
                  (b / 24) * 128, (b % 24) * 128, false, sm);
    } else {
        int r = b - G2_TILES;
        gemm_core(A3, KVL, B3h, B3l, KVW, (float*)0, C3h, C3l, KVW, KVW, KVL,
                  (r / 32) * 128, (r % 32) * 128, true, sm);
    }
}

// ------- RoPE on q + full q split; kpe in tail blocks -------
__global__ __launch_bounds__(256) void rope_qsplit_kernel(
    const float* __restrict__ qf, const float* __restrict__ qc,
    __half* __restrict__ qsh, __half* __restrict__ qsl,
    __half* __restrict__ kpeh, __half* __restrict__ kpel,
    const float* __restrict__ cosb, const float* __restrict__ sinb)
{
    __shared__ float row[QW];
    int b = blockIdx.x;
    if (b < SEQ) {
        const int s = b;
        const float* src = qf + (size_t)s * QW;
#pragma unroll
        for (int i = 0; i < 3; ++i) {
            int idx = (i * 256 + threadIdx.x) * 4;
            *(float4*)(row + idx) = *(const float4*)(src + idx);
        }
        __syncthreads();
        float y0[2], y1[2];
        int hd[2], ln[2];
#pragma unroll
        for (int e = 0; e < 2; ++e) {
            int item = threadIdx.x + e * 256;
            hd[e] = item >> 5; ln[e] = item & 31;
            float c  = cosb[s * DR + ln[e]];
            float sn = sinb[s * DR + ln[e]];
            float x0 = row[hd[e] * DQK + DN + 2 * ln[e]];
            float x1 = row[hd[e] * DQK + DN + 2 * ln[e] + 1];
            y0[e] = x0 * c - x1 * sn;
            y1[e] = x1 * c + x0 * sn;
        }
        __syncthreads();
#pragma unroll
        for (int e = 0; e < 2; ++e) {
            row[hd[e] * DQK + DN + ln[e]]      = y0[e];
            row[hd[e] * DQK + DN + ln[e] + 32] = y1[e];
        }
        __syncthreads();
#pragma unroll
        for (int i = 0; i < 6; ++i) {
            int p = i * 256 + threadIdx.x;
            uint32_t hh, ll;
            split_h2(row[2 * p], row[2 * p + 1], hh, ll);
            ((uint32_t*)qsh)[(size_t)s * (QW / 2) + p] = hh;
            ((uint32_t*)qsl)[(size_t)s * (QW / 2) + p] = ll;
        }
    } else {
        int wr = (b - SEQ) * 8 + (threadIdx.x >> 5);
        int lane = threadIdx.x & 31;
        const float* x = qc + (size_t)wr * FWP + QL + KVL;
        float c  = cosb[wr * DR + lane];
        float sn = sinb[wr * DR + lane];
        float x0 = x[2 * lane], x1 = x[2 * lane + 1];
        float z0 = x0 * c - x1 * sn;
        float z1 = x1 * c + x0 * sn;
        __half h0 = __float2half_rn(z0);
        __half h1 = __float2half_rn(z1);
        kpeh[wr * DR + lane]      = h0;
        kpel[wr * DR + lane]      = __float2half_rn(z0 - __half2float(h0));
        kpeh[wr * DR + lane + 32] = h1;
        kpel[wr * DR + lane + 32] = __float2half_rn(z1 - __half2float(h1));
    }
}

// ==== flash attention BQ=128/BK=64, cp.async phase-pipelined fills ====
#define A_QH 0
#define A_QL 49152
#define A_KH 98304
#define A_KL 122880
#define A_VH 147456
#define A_VL 163840
#define A_PH 180224
#define ATTN_SMEM_BYTES 196608

__global__ __launch_bounds__(256) void attn_mma(
    const __half* __restrict__ qh, const __half* __restrict__ ql,
    const __half* __restrict__ kvh, const __half* __restrict__ kvl,
    const __half* __restrict__ kpeh, const __half* __restrict__ kpel,
    __half* __restrict__ ath)
{
    extern __shared__ char sm[];
    const uint32_t sb = smem_u32(sm);

    const int tid = threadIdx.x, lane = tid & 31, wm = tid >> 5;
    const int qb = gridDim.x - 1 - blockIdx.x;
    const int hh_ = blockIdx.y;
    const int q0 = qb * 128;
    const float scale = rsqrtf((float)DQK);
    const int nkb = 2 * qb + 2;

    auto fill_K = [&](int kb) {
        const int k0 = kb * 64;
#pragma unroll
        for (int i = 0; i < 6; ++i) {
            int idx = i * 256 + tid;
            int r = idx / 24, u = idx % 24;
            uint32_t off = r * 384 + ((u ^ (r & 7)) << 4);
            if (u < 16) {
                const size_t go = (size_t)(k0 + r) * KVW + hh_ * (DN + DV) + u * 8;
                CP_ASYNC16(sb + A_KH + off, kvh + go);
                CP_ASYNC16(sb + A_KL + off, kvl + go);
            } else {
                const size_t go = (size_t)(k0 + r) * DR + (u - 16) * 8;
                CP_ASYNC16(sb + A_KH + off, kpeh + go);
                CP_ASYNC16(sb + A_KL + off, kpel + go);
            }
        }
    };
    auto fill_V = [&](int kb) {
        const int k0 = kb * 64;
#pragma unroll
        for (int i = 0; i < 4; ++i) {
            int idx = i * 256 + tid;
            int r = idx >> 4, u = idx & 15;
            uint32_t off = r * 256 + ((u ^ (r & 7)) << 4);
            const size_t go = (size_t)(k0 + r) * KVW + hh_ * (DN + DV) + DN + u * 8;
            CP_ASYNC16(sb + A_VH + off, kvh + go);
            CP_ASYNC16(sb + A_VL + off, kvl + go);
        }
    };

    fill_K(0); CP_COMMIT();
    fill_V(0); CP_COMMIT();
#pragma unroll
    for (int i = 0; i < 12; ++i) {
        int idx = i * 256 + tid;
        int r = idx / 24, u = idx % 24;
        int off = r * 384 + ((u ^ (r & 7)) << 4);
        const size_t go = (size_t)(q0 + r) * QW + hh_ * DQK + u * 8;
        *(uint4*)(sm + A_QH + off) = *(const uint4*)(qh + go);
        *(uint4*)(sm + A_QL + off) = *(const uint4*)(ql + go);
    }

    const int g = lane >> 2, t = lane & 3;
    const int r0 = wm * 16 + g, r1 = r0 + 8;

    float m0 = -1e30f, m1 = -1e30f, l0 = 0.f, l1 = 0.f;
    float acc_o[16][4];
#pragma unroll
    for (int nt = 0; nt < 16; ++nt)
#pragma unroll
        for (int i = 0; i < 4; ++i) acc_o[nt][i] = 0.f;

    for (int kb = 0; kb < nkb; ++kb) {
        const int k0 = kb * 64;
        const bool more = (kb + 1 < nkb);

        CP_WAIT1();
        __syncthreads();

        float acc_s[8][4];
#pragma unroll
        for (int nt = 0; nt < 8; ++nt)
#pragma unroll
            for (int i = 0; i < 4; ++i) acc_s[nt][i] = 0.f;

#pragma unroll
        for (int ks = 0; ks < 12; ++ks) {
            uint32_t qfh[4], qfl[4];
            {
                int rowi = wm * 16 + (lane & 15);
                int c = 2 * ks + (lane >> 4);
                uint32_t ad = smem_u32(sm + rowi * 384 + ((c ^ (rowi & 7)) << 4));
                LDSM_X4(qfh[0], qfh[1], qfh[2], qfh[3], ad + A_QH);
                LDSM_X4(qfl[0], qfl[1], qfl[2], qfl[3], ad + (A_QL - A_QH));
            }
#pragma unroll
            for (int nt = 0; nt < 8; ++nt) {
                int krow = nt * 8 + (lane & 7);
                int kc = 2 * ks + ((lane >> 3) & 1);
                uint32_t kd = smem_u32(sm + A_KH + krow * 384 + ((kc ^ (krow & 7)) << 4));
                uint32_t kh0, kh1, kl0, kl1;
                LDSM_X2(kh0, kh1, kd);
                LDSM_X2(kl0, kl1, kd + (A_KL - A_KH));
                MMA16816(acc_s[nt], qfh[0], qfh[1], qfh[2], qfh[3], kl0, kl1);
                MMA16816(acc_s[nt], qfl[0], qfl[1], qfl[2], qfl[3], kh0, kh1);
                MMA16816(acc_s[nt], qfh[0], qfh[1], qfh[2], qfh[3], kh0, kh1);
            }
        }
        __syncthreads();
        if (more) fill_K(kb + 1);
        CP_COMMIT();

        float vm0 = -1e30f, vm1 = -1e30f;
#pragma unroll
        for (int nt = 0; nt < 8; ++nt) {
            int col = k0 + nt * 8 + 2 * t;
            float v00 = acc_s[nt][0] * scale, v01 = acc_s[nt][1] * scale;
            float v10 = acc_s[nt][2] * scale, v11 = acc_s[nt][3] * scale;
            if (col     > q0 + r0) v00 = -1e30f;
            if (col + 1 > q0 + r0) v01 = -1e30f;
            if (col     > q0 + r1) v10 = -1e30f;
            if (col + 1 > q0 + r1) v11 = -1e30f;
            acc_s[nt][0] = v00; acc_s[nt][1] = v01;
            acc_s[nt][2] = v10; acc_s[nt][3] = v11;
            vm0 = fmaxf(vm0, fmaxf(v00, v01));
            vm1 = fmaxf(vm1, fmaxf(v10, v11));
        }
        vm0 = fmaxf(vm0, __shfl_xor_sync(0xffffffffu, vm0, 1));
        vm0 = fmaxf(vm0, __shfl_xor_sync(0xffffffffu, vm0, 2));
        vm1 = fmaxf(vm1, __shfl_xor_sync(0xffffffffu, vm1, 1));
        vm1 = fmaxf(vm1, __shfl_xor_sync(0xffffffffu, vm1, 2));

        float mnew0 = fmaxf(m0, vm0);
        float mnew1 = fmaxf(m1, vm1);
        float alpha0 = __expf(m0 - mnew0);
        float alpha1 = __expf(m1 - mnew1);
        m0 = mnew0; m1 = mnew1;

        float s0 = 0.f, s1 = 0.f;
#pragma unroll
        for (int nt = 0; nt < 8; ++nt) {
            float p00 = __expf(acc_s[nt][0] - mnew0);
            float p01 = __expf(acc_s[nt][1] - mnew0);
            float p10 = __expf(acc_s[nt][2] - mnew1);
            float p11 = __expf(acc_s[nt][3] - mnew1);
            s0 += p00 + p01;
            s1 += p10 + p11;
            int off0 = r0 * 128 + ((nt ^ (r0 & 7)) << 4) + t * 4;
            *(__half2*)(sm + A_PH + off0) = __float22half2_rn(make_float2(p00, p01));
            int off1 = r1 * 128 + ((nt ^ (r1 & 7)) << 4) + t * 4;
            *(__half2*)(sm + A_PH + off1) = __float22half2_rn(make_float2(p10, p11));
        }
        s0 += __shfl_xor_sync(0xffffffffu, s0, 1);
        s0 += __shfl_xor_sync(0xffffffffu, s0, 2);
        s1 += __shfl_xor_sync(0xffffffffu, s1, 1);
        s1 += __shfl_xor_sync(0xffffffffu, s1, 2);
        l0 = l0 * alpha0 + s0;
        l1 = l1 * alpha1 + s1;
        __syncwarp();

        if (more) { CP_WAIT1(); } else { CP_WAIT0(); }
        __syncthreads();

#pragma unroll
        for (int nt = 0; nt < 16; ++nt) {
            acc_o[nt][0] *= alpha0; acc_o[nt][1] *= alpha0;
            acc_o[nt][2] *= alpha1; acc_o[nt][3] *= alpha1;
        }
#pragma unroll
        for (int ks = 0; ks < 4; ++ks) {
            uint32_t ph[4];
            {
                int rowi = wm * 16 + (lane & 15);
                int c = 2 * ks + (lane >> 4);
                uint32_t pd = smem_u32(sm + A_PH + rowi * 128 + ((c ^ (rowi & 7)) << 4));
                LDSM_X4(ph[0], ph[1], ph[2], ph[3], pd);
            }
#pragma unroll
            for (int pr = 0; pr < 8; ++pr) {
                int vk = ks * 16 + (lane & 15);
                int vc = pr * 2 + (lane >> 4);
                uint32_t vd = smem_u32(sm + A_VH + vk * 256 + ((vc ^ (vk & 7)) << 4));
                uint32_t b0, b1, b2, b3, c0, c1, c2, c3;
                LDSM_X4_T(b0, b1, b2, b3, vd);
                LDSM_X4_T(c0, c1, c2, c3, vd + (A_VL - A_VH));
                int nt0 = 2 * pr, nt1 = 2 * pr + 1;
                MMA16816(acc_o[nt0], ph[0], ph[1], ph[2], ph[3], c0, c1);
                MMA16816(acc_o[nt0], ph[0], ph[1], ph[2], ph[3], b0, b1);
                MMA16816(acc_o[nt1], ph[0], ph[1], ph[2], ph[3], c2, c3);
                MMA16816(acc_o[nt1], ph[0], ph[1], ph[2], ph[3], b2, b3);
            }
        }
        __syncthreads();
        if (more) fill_V(kb + 1);
        CP_COMMIT();
    }

    float inv0 = 1.f / l0;
    float inv1 = 1.f / l1;
#pragma unroll
    for (int nt = 0; nt < 16; ++nt) {
        int col = nt * 8 + 2 * t;
        *(__half2*)(ath + (size_t)(q0 + r0) * AW + hh_ * DV + col) =
            __float22half2_rn(make_float2(acc_o[nt][0] * inv0, acc_o[nt][1] * inv0));
        *(__half2*)(ath + (size_t)(q0 + r1) * AW + hh_ * DV + col) =
            __float22half2_rn(make_float2(acc_o[nt][2] * inv1, acc_o[nt][3] * inv1));
    }
}

// ---------------- launch ----------------
extern "C" void kernel_launch(void* const* d_in, const int* in_sizes, int n_in,
                              void* d_out, int out_size)
{
    const float* hidden = (const float*)d_in[0];
    const float* cosb   = (const float*)d_in[1];
    const float* sinb   = (const float*)d_in[2];
    const float* w_qa   = (const float*)d_in[3];
    const float* gm_qa  = (const float*)d_in[4];
    const float* w_qb   = (const float*)d_in[5];
    const float* w_kva  = (const float*)d_in[6];
    const float* gm_kva = (const float*)d_in[7];
    const float* w_kvb  = (const float*)d_in[8];
    const float* w_o    = (const float*)d_in[9];
    float* out = (float*)d_out;

    float *qc, *qf;
    __half *hidh, *wfh, *wfl, *qbh, *qbl, *kvbh, *kvbl, *oh, *ol;
    __half *qanh, *cknh, *qsh, *qsl, *kvh, *kvl, *kpeh, *kpel, *ath;
    cudaGetSymbolAddress((void**)&qc,   g_qc_s);
    cudaGetSymbolAddress((void**)&qf,   g_q_s);
    cudaGetSymbolAddress((void**)&hidh, g_hid_h);
    cudaGetSymbolAddress((void**)&wfh,  g_wf_h);  cudaGetSymbolAddress((void**)&wfl,  g_wf_l);
    cudaGetSymbolAddress((void**)&qbh,  g_qb_h);  cudaGetSymbolAddress((void**)&qbl,  g_qb_l);
    cudaGetSymbolAddress((void**)&kvbh, g_kvb_h); cudaGetSymbolAddress((void**)&kvbl, g_kvb_l);
    cudaGetSymbolAddress((void**)&oh,   g_o_h);   cudaGetSymbolAddress((void**)&ol,   g_o_l);
    cudaGetSymbolAddress((void**)&qanh, g_qan_h);
    cudaGetSymbolAddress((void**)&cknh, g_ckn_h);
    cudaGetSymbolAddress((void**)&qsh,  g_qs_h);  cudaGetSymbolAddress((void**)&qsl,  g_qs_l);
    cudaGetSymbolAddress((void**)&kvh,  g_kv_h);  cudaGetSymbolAddress((void**)&kvl,  g_kv_l);
    cudaGetSymbolAddress((void**)&kpeh, g_kpe_h); cudaGetSymbolAddress((void**)&kpel, g_kpe_l);
    cudaGetSymbolAddress((void**)&ath,  g_at_h);

    static bool attr_done = false;
    if (!attr_done) {
        cudaFuncSetAttribute(attn_mma, cudaFuncAttributeMaxDynamicSharedMemorySize,
                             ATTN_SMEM_BYTES);
        cudaFuncSetAttribute(gemm_f32out, cudaFuncAttributeMaxDynamicSharedMemorySize,
                             GEMM_SMEM_BYTES);
        cudaFuncSetAttribute(gemm_dual, cudaFuncAttributeMaxDynamicSharedMemorySize,
                             GEMM_SMEM_BYTES);
        attr_done = true;
    }

    prep_kernel<<<PREP_BLOCKS, 256>>>(hidden, w_qa, w_kva, w_qb, w_kvb, w_o,
                                      hidh, wfh, wfl, qbh, qbl, kvbh, kvbl, oh, ol);
    gemm_f32out<<<dim3(FWP / 128, SEQ / 128), 256, GEMM_SMEM_BYTES>>>(
        hidh, HID, wfh, wfl, FWP, qc, FWP, FW, HID);
    rmsnorm2_kernel<<<SEQ, 256>>>(qc, gm_qa, gm_kva, qanh, cknh);
    gemm_dual<<<G2_TILES + G3_TILES, 256, GEMM_SMEM_BYTES>>>(
        qanh, qbh, qbl, qf, cknh, kvbh, kvbl, kvh, kvl);
    rope_qsplit_kernel<<<SEQ + 256, 256>>>(qf, qc, qsh, qsl, kpeh, kpel, cosb, sinb);
    attn_mma<<<dim3(SEQ / 128, NH), 256, ATTN_SMEM_BYTES>>>(
        qsh, qsl, kvh, kvl, kpeh, kpel, ath);
    gemm_f32out<<<dim3(HID / 128, SEQ / 128), 256, GEMM_SMEM_BYTES>>>(
        ath, AW, oh, ol, HID, out, HID, HID, AW);
}

// round 14
// speedup vs baseline: 1.0309x; 1.0309x over previous
#include <cuda_runtime.h>
#include <cuda_fp16.h>
#include <cuda_bf16.h>
#include <stdint.h>
#include <math.h>

#define SEQ 2048
#define HID 2048
#define NH 16
#define QL 1536
#define KVL 512
#define DN 128
#define DR 64
#define DV 128
#define DQK 192
#define CKVW (KVL + DR)      // 576
#define FW (QL + CKVW)       // 2112
#define FWP 2176
#define QW (NH * DQK)        // 3072
#define KVW (NH * (DN + DV)) // 4096
#define AW (NH * DV)         // 2048

// ---------------- scratch ----------------
__device__ float  g_qc_s [(size_t)SEQ * FWP];
__device__ float  g_q_s  [(size_t)SEQ * QW];
__device__ __half g_hid_h[(size_t)SEQ * HID];
__device__ __half g_wf_h [(size_t)HID * FWP],  g_wf_l [(size_t)HID * FWP];
__device__ __half g_qb_h [(size_t)QL * QW],    g_qb_l [(size_t)QL * QW];
__device__ __half g_kvb_h[(size_t)KVL * KVW],  g_kvb_l[(size_t)KVL * KVW];
__device__ __half g_o_h  [(size_t)AW * HID],   g_o_l  [(size_t)AW * HID];
__device__ __half g_qan_h[(size_t)SEQ * QL];
__device__ __half g_ckn_h[(size_t)SEQ * KVL];
__device__ __half g_qs_h [(size_t)SEQ * QW],   g_qs_l [(size_t)SEQ * QW];
__device__ __half g_kv_h [(size_t)SEQ * KVW],  g_kv_l [(size_t)SEQ * KVW];
__device__ __half g_kpe_h[(size_t)SEQ * DR],   g_kpe_l[(size_t)SEQ * DR];
__device__ __half g_at_h [(size_t)SEQ * AW];

__device__ __forceinline__ uint32_t smem_u32(const void* p) {
    return (uint32_t)__cvta_generic_to_shared(p);
}

#define LDSM_X4(r0, r1, r2, r3, a)                                            \
    asm volatile("ldmatrix.sync.aligned.m8n8.x4.shared.b16 {%0,%1,%2,%3},[%4];" \
                 : "=r"(r0), "=r"(r1), "=r"(r2), "=r"(r3) : "r"(a))
#define LDSM_X2(r0, r1, a)                                                    \
    asm volatile("ldmatrix.sync.aligned.m8n8.x2.shared.b16 {%0,%1},[%2];"     \
                 : "=r"(r0), "=r"(r1) : "r"(a))
#define LDSM_X4_T(r0, r1, r2, r3, a)                                          \
    asm volatile("ldmatrix.sync.aligned.m8n8.x4.trans.shared.b16 {%0,%1,%2,%3},[%4];" \
                 : "=r"(r0), "=r"(r1), "=r"(r2), "=r"(r3) : "r"(a))

#define MMA16816(d, a0, a1, a2, a3, b0, b1)                                   \
    asm volatile("mma.sync.aligned.m16n8k16.row.col.f32.f16.f16.f32 "         \
                 "{%0,%1,%2,%3},{%4,%5,%6,%7},{%8,%9},{%0,%1,%2,%3};"          \
                 : "+f"(d[0]), "+f"(d[1]), "+f"(d[2]), "+f"(d[3])              \
                 : "r"(a0), "r"(a1), "r"(a2), "r"(a3), "r"(b0), "r"(b1))

#define CP_ASYNC16(dst, src)                                                  \
    asm volatile("cp.async.cg.shared.global [%0], [%1], 16;" :: "r"(dst), "l"(src))
#define CP_COMMIT() asm volatile("cp.async.commit_group;" ::: "memory")
#define CP_WAIT1()  asm volatile("cp.async.wait_group 1;" ::: "memory")
#define CP_WAIT0()  asm volatile("cp.async.wait_group 0;" ::: "memory")

__device__ __forceinline__ void split_h2(float x, float y, uint32_t& h, uint32_t& l) {
    __half hx = __float2half_rn(x), hy = __float2half_rn(y);
    __half2 hp = __halves2half2(hx, hy);
    h = *(uint32_t*)&hp;
    __half2 lp = __halves2half2(__float2half_rn(x - __half2float(hx)),
                                __float2half_rn(y - __half2float(hy)));
    l = *(uint32_t*)&lp;
}

// ======== prep kernel, 4-way ILP (latency-bound fix) ========
// Each thread handles 4 independent float2 -> h/l pairs.
#define PNB1 2048    // hconv:  SEQ*HID/2/1024
#define PNB2 2176    // wfuse:  HID*FWP/2/1024
#define PNB3 2304    // qb:     QL*QW/2/1024
#define PNB4 1024    // kvb:    KVL*KVW/2/1024
#define PNB5 2048    // wo:     AW*HID/2/1024
#define PREP_BLOCKS (PNB1 + PNB2 + PNB3 + PNB4 + PNB5)

__global__ __launch_bounds__(256) void prep_kernel(
    const float* __restrict__ hidden,
    const float* __restrict__ wqa, const float* __restrict__ wkva,
    const float* __restrict__ wqb, const float* __restrict__ wkvb,
    const float* __restrict__ wo,
    __half* __restrict__ hidh,
    __half* __restrict__ wfh, __half* __restrict__ wfl,
    __half* __restrict__ qbh, __half* __restrict__ qbl,
    __half* __restrict__ kvbh, __half* __restrict__ kvbl,
    __half* __restrict__ oh, __half* __restrict__ ol)
{
    int b = blockIdx.x;
    if (b < PNB1) {
        int i0 = b * 1024 + threadIdx.x;
        float2 v[4];
#pragma unroll
        for (int e = 0; e < 4; ++e) v[e] = ((const float2*)hidden)[i0 + e * 256];
#pragma unroll
        for (int e = 0; e < 4; ++e)
            ((__half2*)hidh)[i0 + e * 256] = __float22half2_rn(v[e]);
    } else if (b < PNB1 + PNB2) {
        int i0 = (b - PNB1) * 1024 + threadIdx.x;
        float2 v[4];
#pragma unroll
        for (int e = 0; e < 4; ++e) {
            int i = i0 + e * 256;
            int row = i / (FWP / 2), p = i % (FWP / 2);
            int col = 2 * p;
            float x = 0.f, y = 0.f;
            if (col < QL)      { x = wqa[(size_t)row * QL + col];         y = wqa[(size_t)row * QL + col + 1]; }
            else if (col < FW) { x = wkva[(size_t)row * CKVW + col - QL]; y = wkva[(size_t)row * CKVW + col - QL + 1]; }
            v[e] = make_float2(x, y);
        }
#pragma unroll
        for (int e = 0; e < 4; ++e) {
            uint32_t hh, ll;
            split_h2(v[e].x, v[e].y, hh, ll);
            ((uint32_t*)wfh)[i0 + e * 256] = hh;
            ((uint32_t*)wfl)[i0 + e * 256] = ll;
        }
    } else if (b < PNB1 + PNB2 + PNB3) {
        int i0 = (b - PNB1 - PNB2) * 1024 + threadIdx.x;
        float2 v[4];
#pragma unroll
        for (int e = 0; e < 4; ++e) v[e] = ((const float2*)wqb)[i0 + e * 256];
#pragma unroll
        for (int e = 0; e < 4; ++e) {
            uint32_t hh, ll;
            split_h2(v[e].x, v[e].y, hh, ll);
            ((uint32_t*)qbh)[i0 + e * 256] = hh;
            ((uint32_t*)qbl)[i0 + e * 256] = ll;
        }
    } else if (b < PNB1 + PNB2 + PNB3 + PNB4) {
        int i0 = (b - PNB1 - PNB2 - PNB3) * 1024 + threadIdx.x;
        float2 v[4];
#pragma unroll
        for (int e = 0; e < 4; ++e) v[e] = ((const float2*)wkvb)[i0 + e * 256];
#pragma unroll
        for (int e = 0; e < 4; ++e) {
            uint32_t hh, ll;
            split_h2(v[e].x, v[e].y, hh, ll);
            ((uint32_t*)kvbh)[i0 + e * 256] = hh;
            ((uint32_t*)kvbl)[i0 + e * 256] = ll;
        }
    } else {
        int i0 = (b - PNB1 - PNB2 - PNB3 - PNB4) * 1024 + threadIdx.x;
        float2 v[4];
#pragma unroll
        for (int e = 0; e < 4; ++e) v[e] = ((const float2*)wo)[i0 + e * 256];
#pragma unroll
        for (int e = 0; e < 4; ++e) {
            uint32_t hh, ll;
            split_h2(v[e].x, v[e].y, hh, ll);
            ((uint32_t*)oh)[i0 + e * 256] = hh;
            ((uint32_t*)ol)[i0 + e * 256] = ll;
        }
    }
}

// ---------------- both RMSNorms ----------------
__global__ __launch_bounds__(256) void rmsnorm2_kernel(
    const float* __restrict__ qc, const float* __restrict__ gqa,
    const float* __restrict__ gkva, __half* __restrict__ qanh,
    __half* __restrict__ cknh)
{
    __shared__ float red[256];
    const float* p = qc + (size_t)blockIdx.x * FWP;
    float s = 0.f;
    for (int i = threadIdx.x; i < QL; i += 256) { float v = p[i]; s += v * v; }
    red[threadIdx.x] = s;
    __syncthreads();
#pragma unroll
    for (int off = 128; off > 0; off >>= 1) {
        if (threadIdx.x < off) red[threadIdx.x] += red[threadIdx.x + off];
        __syncthreads();
    }
    float inv = rsqrtf(red[0] / (float)QL + 1e-6f);
    for (int i = threadIdx.x; i < QL / 2; i += 256) {
        float v0 = p[2 * i] * inv * gqa[2 * i];
        float v1 = p[2 * i + 1] * inv * gqa[2 * i + 1];
        ((__half2*)qanh)[(size_t)blockIdx.x * (QL / 2) + i] = __float22half2_rn(make_float2(v0, v1));
    }
    __syncthreads();
    const float* p2 = p + QL;
    s = 0.f;
    for (int i = threadIdx.x; i < KVL; i += 256) { float v = p2[i]; s += v * v; }
    red[threadIdx.x] = s;
    __syncthreads();
#pragma unroll
    for (int off = 128; off > 0; off >>= 1) {
        if (threadIdx.x < off) red[threadIdx.x] += red[threadIdx.x + off];
        __syncthreads();
    }
    inv = rsqrtf(red[0] / (float)KVL + 1e-6f);
    for (int i = threadIdx.x; i < KVL / 2; i += 256) {
        float v0 = p2[2 * i] * inv * gkva[2 * i];
        float v1 = p2[2 * i + 1] * inv * gkva[2 * i + 1];
        ((__half2*)cknh)[(size_t)blockIdx.x * (KVL / 2) + i] = __float22half2_rn(make_float2(v0, v1));
    }
}

// ======== fp16x2 GEMM core (R12 config: 2-stage K64 ring, 2 CTAs/SM) ========
#define G_AT 16384
#define G_BT 16384
#define G_STAGE (G_AT + 2 * G_BT)        // 49152
#define GEMM_SMEM_BYTES (2 * G_STAGE)    // 98304

__device__ __forceinline__ void gemm_core(
    const __half* __restrict__ Ah, int lda,
    const __half* __restrict__ Bh, const __half* __restrict__ Bl, int ldb,
    float* __restrict__ C, __half* __restrict__ Ch, __half* __restrict__ Cl,
    int ldc, int N, int K, int row0, int col0, bool split_out, char* sm)
{
    const uint32_t sbase = smem_u32(sm);
    const int tid  = threadIdx.x;
    const int lane = tid & 31, w = tid >> 5;
    const int wm = w & 3, wn = w >> 2;

    float acc[2][8][4];
#pragma unroll
    for (int mt = 0; mt < 2; ++mt)
#pragma unroll
        for (int nt = 0; nt < 8; ++nt)
#pragma unroll
            for (int i = 0; i < 4; ++i) acc[mt][nt][i] = 0.f;

    auto do_cp = [&](int stage, int k0) {
        uint32_t sb = sbase + stage * G_STAGE;
#pragma unroll
        for (int i = 0; i < 4; ++i) {
            int idx = i * 256 + tid;
            int r = idx >> 3, u = idx & 7;
            uint32_t off = r * 128 + ((u ^ (r & 7)) << 4);
            CP_ASYNC16(sb + off, Ah + (size_t)(row0 + r) * lda + k0 + u * 8);
        }
#pragma unroll
        for (int i = 0; i < 4; ++i) {
            int idx = i * 256 + tid;
            int r = idx >> 4, u = idx & 15;
            uint32_t off = G_AT + r * 256 + ((u ^ (r & 7)) << 4);
            CP_ASYNC16(sb + off, Bh + (size_t)(k0 + r) * ldb + col0 + u * 8);
            CP_ASYNC16(sb + G_BT + off, Bl + (size_t)(k0 + r) * ldb + col0 + u * 8);
        }
    };

    const int nIter = K >> 6;
    do_cp(0, 0);
    CP_COMMIT();
    if (nIter > 1) do_cp(1, 64);
    CP_COMMIT();

    for (int it = 0; it < nIter; ++it) {
        CP_WAIT1();
        __syncthreads();

        char* base = sm + (it & 1) * G_STAGE;
#pragma unroll
        for (int kg = 0; kg < 4; ++kg) {
            uint32_t ah[2][4];
#pragma unroll
            for (int mt = 0; mt < 2; ++mt) {
                int row = wm * 32 + mt * 16 + (lane & 15);
                int kc = kg * 2 + (lane >> 4);
                uint32_t ad = smem_u32(base + row * 128 + ((kc ^ (row & 7)) << 4));
                LDSM_X4(ah[mt][0], ah[mt][1], ah[mt][2], ah[mt][3], ad);
            }
            uint32_t bh[8][2], bl[8][2];
#pragma unroll
            for (int pr = 0; pr < 4; ++pr) {
                int k = kg * 16 + (lane & 15);
                int nc = wn * 8 + pr * 2 + (lane >> 4);
                uint32_t bd = smem_u32(base + G_AT + k * 256 + ((nc ^ (k & 7)) << 4));
                uint32_t t0, t1, t2, t3;
                LDSM_X4_T(t0, t1, t2, t3, bd);
                bh[2 * pr][0] = t0; bh[2 * pr][1] = t1;
                bh[2 * pr + 1][0] = t2; bh[2 * pr + 1][1] = t3;
                LDSM_X4_T(t0, t1, t2, t3, bd + G_BT);
                bl[2 * pr][0] = t0; bl[2 * pr][1] = t1;
                bl[2 * pr + 1][0] = t2; bl[2 * pr + 1][1] = t3;
            }
#pragma unroll
            for (int mt = 0; mt < 2; ++mt)
#pragma unroll
                for (int nt = 0; nt < 8; ++nt) {
                    MMA16816(acc[mt][nt], ah[mt][0], ah[mt][1], ah[mt][2], ah[mt][3],
                             bl[nt][0], bl[nt][1]);
                    MMA16816(acc[mt][nt], ah[mt][0], ah[mt][1], ah[mt][2], ah[mt][3],
                             bh[nt][0], bh[nt][1]);
                }
        }
        __syncthreads();
        if (it + 2 < nIter) {
            do_cp(it & 1, (it + 2) << 6);
            CP_COMMIT();
        }
    }

    const int g = lane >> 2, t = lane & 3;
#pragma unroll
    for (int mt = 0; mt < 2; ++mt) {
        int r = row0 + wm * 32 + mt * 16 + g;
#pragma unroll
        for (int nt = 0; nt < 8; ++nt) {
            int c = col0 + wn * 64 + nt * 8 + 2 * t;
            if (split_out) {
                uint32_t hh, ll;
                split_h2(acc[mt][nt][0], acc[mt][nt][1], hh, ll);
                *(uint32_t*)(Ch + (size_t)r * ldc + c) = hh;
                *(uint32_t*)(Cl + (size_t)r * ldc + c) = ll;
                split_h2(acc[mt][nt][2], acc[mt][nt][3], hh, ll);
                *(uint32_t*)(Ch + (size_t)(r + 8) * ldc + c) = hh;
                *(uint32_t*)(Cl + (size_t)(r + 8) * ldc + c) = ll;
            } else if (c < N) {
                *(float2*)(C + (size_t)r * ldc + c)       = make_float2(acc[mt][nt][0], acc[mt][nt][1]);
                *(float2*)(C + (size_t)(r + 8) * ldc + c) = make_float2(acc[mt][nt][2], acc[mt][nt][3]);
            }
        }
    }
}

__global__ __launch_bounds__(256, 2) void gemm_f32out(
    const __half* __restrict__ Ah, int lda,
    const __half* __restrict__ Bh, const __half* __restrict__ Bl, int ldb,
    float* __restrict__ C, int ldc, int N, int K)
{
    extern __shared__ char sm[];
    gemm_core(Ah, lda, Bh, Bl, ldb, C, (__half*)0, (__half*)0, ldc, N, K,
              blockIdx.y * 128, blockIdx.x * 128, false, sm);
}

#define G2_TILES 384
#define G3_TILES 512
__global__ __launch_bounds__(256, 2) void gemm_dual(
    const __half* __restrict__ A2, const __half* __restrict__ B2h,
    const __half* __restrict__ B2l, float* __restrict__ C2,
    const __half* __restrict__ A3, const __half* __restrict__ B3h,
    const __half* __restrict__ B3l, __half* __restrict__ C3h, __half* __restrict__ C3l)
{
    extern __shared__ char sm[];
    int b = blockIdx.x;
    if (b < G2_TILES) {
        gemm_core(A2, QL, B2h, B2l, QW, C2, (__half*)0, (__half*)0, QW, QW, QL,
                  (b / 24) * 128, (b % 24) * 128, false, sm);
    } else {
        int r = b - G2_TILES;
        gemm_core(A3, KVL, B3h, B3l, KVW, (float*)0, C3h, C3l, KVW, KVW, KVL,
                  (r / 32) * 128, (r % 32) * 128, true, sm);
    }
}

// ------- RoPE on q + full q split; kpe in tail blocks -------
__global__ __launch_bounds__(256) void rope_qsplit_kernel(
    const float* __restrict__ qf, const float* __restrict__ qc,
    __half* __restrict__ qsh, __half* __restrict__ qsl,
    __half* __restrict__ kpeh, __half* __restrict__ kpel,
    const float* __restrict__ cosb, const float* __restrict__ sinb)
{
    __shared__ float row[QW];
    int b = blockIdx.x;
    if (b < SEQ) {
        const int s = b;
        const float* src = qf + (size_t)s * QW;
#pragma unroll
        for (int i = 0; i < 3; ++i) {
            int idx = (i * 256 + threadIdx.x) * 4;
            *(float4*)(row + idx) = *(const float4*)(src + idx);
        }
        __syncthreads();
        float y0[2], y1[2];
        int hd[2], ln[2];
#pragma unroll
        for (int e = 0; e < 2; ++e) {
            int item = threadIdx.x + e * 256;
            hd[e] = item >> 5; ln[e] = item & 31;
            float c  = cosb[s * DR + ln[e]];
            float sn = sinb[s * DR + ln[e]];
            float x0 = row[hd[e] * DQK + DN + 2 * ln[e]];
            float x1 = row[hd[e] * DQK + DN + 2 * ln[e] + 1];
            y0[e] = x0 * c - x1 * sn;
            y1[e] = x1 * c + x0 * sn;
        }
        __syncthreads();
#pragma unroll
        for (int e = 0; e < 2; ++e) {
            row[hd[e] * DQK + DN + ln[e]]      = y0[e];
            row[hd[e] * DQK + DN + ln[e] + 32] = y1[e];
        }
        __syncthreads();
#pragma unroll
        for (int i = 0; i < 6; ++i) {
            int p = i * 256 + threadIdx.x;
            uint32_t hh, ll;
            split_h2(row[2 * p], row[2 * p + 1], hh, ll);
            ((uint32_t*)qsh)[(size_t)s * (QW / 2) + p] = hh;
            ((uint32_t*)qsl)[(size_t)s * (QW / 2) + p] = ll;
        }
    } else {
        int wr = (b - SEQ) * 8 + (threadIdx.x >> 5);
        int lane = threadIdx.x & 31;
        const float* x = qc + (size_t)wr * FWP + QL + KVL;
        float c  = cosb[wr * DR + lane];
        float sn = sinb[wr * DR + lane];
        float x0 = x[2 * lane], x1 = x[2 * lane + 1];
        float z0 = x0 * c - x1 * sn;
        float z1 = x1 * c + x0 * sn;
        __half h0 = __float2half_rn(z0);
        __half h1 = __float2half_rn(z1);
        kpeh[wr * DR + lane]      = h0;
        kpel[wr * DR + lane]      = __float2half_rn(z0 - __half2float(h0));
        kpeh[wr * DR + lane + 32] = h1;
        kpel[wr * DR + lane + 32] = __float2half_rn(z1 - __half2float(h1));
    }
}

// ==== flash attention BQ=128/BK=64, cp.async phase-pipelined fills ====
#define A_QH 0
#define A_QL 49152
#define A_KH 98304
#define A_KL 122880
#define A_VH 147456
#define A_VL 163840
#define A_PH 180224
#define ATTN_SMEM_BYTES 196608

__global__ __launch_bounds__(256) void attn_mma(
    const __half* __restrict__ qh, const __half* __restrict__ ql,
    const __half* __restrict__ kvh, const __half* __restrict__ kvl,
    const __half* __restrict__ kpeh, const __half* __restrict__ kpel,
    __half* __restrict__ ath)
{
    extern __shared__ char sm[];
    const uint32_t sb = smem_u32(sm);

    const int tid = threadIdx.x, lane = tid & 31, wm = tid >> 5;
    const int qb = gridDim.x - 1 - blockIdx.x;
    const int hh_ = blockIdx.y;
    const int q0 = qb * 128;
    const float scale = rsqrtf((float)DQK);
    const int nkb = 2 * qb + 2;

    auto fill_K = [&](int kb) {
        const int k0 = kb * 64;
#pragma unroll
        for (int i = 0; i < 6; ++i) {
            int idx = i * 256 + tid;
            int r = idx / 24, u = idx % 24;
            uint32_t off = r * 384 + ((u ^ (r & 7)) << 4);
            if (u < 16) {
                const size_t go = (size_t)(k0 + r) * KVW + hh_ * (DN + DV) + u * 8;
                CP_ASYNC16(sb + A_KH + off, kvh + go);
                CP_ASYNC16(sb + A_KL + off, kvl + go);
            } else {
                const size_t go = (size_t)(k0 + r) * DR + (u - 16) * 8;
                CP_ASYNC16(sb + A_KH + off, kpeh + go);
                CP_ASYNC16(sb + A_KL + off, kpel + go);
            }
        }
    };
    auto fill_V = [&](int kb) {
        const int k0 = kb * 64;
#pragma unroll
        for (int i = 0; i < 4; ++i) {
            int idx = i * 256 + tid;
            int r = idx >> 4, u = idx & 15;
            uint32_t off = r * 256 + ((u ^ (r & 7)) << 4);
            const size_t go = (size_t)(k0 + r) * KVW + hh_ * (DN + DV) + DN + u * 8;
            CP_ASYNC16(sb + A_VH + off, kvh + go);
            CP_ASYNC16(sb + A_VL + off, kvl + go);
        }
    };

    fill_K(0); CP_COMMIT();
    fill_V(0); CP_COMMIT();
#pragma unroll
    for (int i = 0; i < 12; ++i) {
        int idx = i * 256 + tid;
        int r = idx / 24, u = idx % 24;
        int off = r * 384 + ((u ^ (r & 7)) << 4);
        const size_t go = (size_t)(q0 + r) * QW + hh_ * DQK + u * 8;
        *(uint4*)(sm + A_QH + off) = *(const uint4*)(qh + go);
        *(uint4*)(sm + A_QL + off) = *(const uint4*)(ql + go);
    }

    const int g = lane >> 2, t = lane & 3;
    const int r0 = wm * 16 + g, r1 = r0 + 8;

    float m0 = -1e30f, m1 = -1e30f, l0 = 0.f, l1 = 0.f;
    float acc_o[16][4];
#pragma unroll
    for (int nt = 0; nt < 16; ++nt)
#pragma unroll
        for (int i = 0; i < 4; ++i) acc_o[nt][i] = 0.f;

    for (int kb = 0; kb < nkb; ++kb) {
        const int k0 = kb * 64;
        const bool more = (kb + 1 < nkb);

        CP_WAIT1();
        __syncthreads();

        float acc_s[8][4];
#pragma unroll
        for (int nt = 0; nt < 8; ++nt)
#pragma unroll
            for (int i = 0; i < 4; ++i) acc_s[nt][i] = 0.f;

#pragma unroll
        for (int ks = 0; ks < 12; ++ks) {
            uint32_t qfh[4], qfl[4];
            {
                int rowi = wm * 16 + (lane & 15);
                int c = 2 * ks + (lane >> 4);
                uint32_t ad = smem_u32(sm + rowi * 384 + ((c ^ (rowi & 7)) << 4));
                LDSM_X4(qfh[0], qfh[1], qfh[2], qfh[3], ad + A_QH);
                LDSM_X4(qfl[0], qfl[1], qfl[2], qfl[3], ad + (A_QL - A_QH));
            }
#pragma unroll
            for (int nt = 0; nt < 8; ++nt) {
                int krow = nt * 8 + (lane & 7);
                int kc = 2 * ks + ((lane >> 3) & 1);
                uint32_t kd = smem_u32(sm + A_KH + krow * 384 + ((kc ^ (krow & 7)) << 4));
                uint32_t kh0, kh1, kl0, kl1;
                LDSM_X2(kh0, kh1, kd);
                LDSM_X2(kl0, kl1, kd + (A_KL - A_KH));
                MMA16816(acc_s[nt], qfh[0], qfh[1], qfh[2], qfh[3], kl0, kl1);
                MMA16816(acc_s[nt], qfl[0], qfl[1], qfl[2], qfl[3], kh0, kh1);
                MMA16816(acc_s[nt], qfh[0], qfh[1], qfh[2], qfh[3], kh0, kh1);
            }
        }
        __syncthreads();
        if (more) fill_K(kb + 1);
        CP_COMMIT();

        float vm0 = -1e30f, vm1 = -1e30f;
#pragma unroll
        for (int nt = 0; nt < 8; ++nt) {
            int col = k0 + nt * 8 + 2 * t;
            float v00 = acc_s[nt][0] * scale, v01 = acc_s[nt][1] * scale;
            float v10 = acc_s[nt][2] * scale, v11 = acc_s[nt][3] * scale;
            if (col     > q0 + r0) v00 = -1e30f;
            if (col + 1 > q0 + r0) v01 = -1e30f;
            if (col     > q0 + r1) v10 = -1e30f;
            if (col + 1 > q0 + r1) v11 = -1e30f;
            acc_s[nt][0] = v00; acc_s[nt][1] = v01;
            acc_s[nt][2] = v10; acc_s[nt][3] = v11;
            vm0 = fmaxf(vm0, fmaxf(v00, v01));
            vm1 = fmaxf(vm1, fmaxf(v10, v11));
        }
        vm0 = fmaxf(vm0, __shfl_xor_sync(0xffffffffu, vm0, 1));
        vm0 = fmaxf(vm0, __shfl_xor_sync(0xffffffffu, vm0, 2));
        vm1 = fmaxf(vm1, __shfl_xor_sync(0xffffffffu, vm1, 1));
        vm1 = fmaxf(vm1, __shfl_xor_sync(0xffffffffu, vm1, 2));

        float mnew0 = fmaxf(m0, vm0);
        float mnew1 = fmaxf(m1, vm1);
        float alpha0 = __expf(m0 - mnew0);
        float alpha1 = __expf(m1 - mnew1);
        m0 = mnew0; m1 = mnew1;

        float s0 = 0.f, s1 = 0.f;
#pragma unroll
        for (int nt = 0; nt < 8; ++nt) {
            float p00 = __expf(acc_s[nt][0] - mnew0);
            float p01 = __expf(acc_s[nt][1] - mnew0);
            float p10 = __expf(acc_s[nt][2] - mnew1);
            float p11 = __expf(acc_s[nt][3] - mnew1);
            s0 += p00 + p01;
            s1 += p10 + p11;
            int off0 = r0 * 128 + ((nt ^ (r0 & 7)) << 4) + t * 4;
            *(__half2*)(sm + A_PH + off0) = __float22half2_rn(make_float2(p00, p01));
            int off1 = r1 * 128 + ((nt ^ (r1 & 7)) << 4) + t * 4;
            *(__half2*)(sm + A_PH + off1) = __float22half2_rn(make_float2(p10, p11));
        }
        s0 += __shfl_xor_sync(0xffffffffu, s0, 1);
        s0 += __shfl_xor_sync(0xffffffffu, s0, 2);
        s1 += __shfl_xor_sync(0xffffffffu, s1, 1);
        s1 += __shfl_xor_sync(0xffffffffu, s1, 2);
        l0 = l0 * alpha0 + s0;
        l1 = l1 * alpha1 + s1;
        __syncwarp();

        if (more) { CP_WAIT1(); } else { CP_WAIT0(); }
        __syncthreads();

#pragma unroll
        for (int nt = 0; nt < 16; ++nt) {
            acc_o[nt][0] *= alpha0; acc_o[nt][1] *= alpha0;
            acc_o[nt][2] *= alpha1; acc_o[nt][3] *= alpha1;
        }
#pragma unroll
        for (int ks = 0; ks < 4; ++ks) {
            uint32_t ph[4];
            {
                int rowi = wm * 16 + (lane & 15);
                int c = 2 * ks + (lane >> 4);
                uint32_t pd = smem_u32(sm + A_PH + rowi * 128 + ((c ^ (rowi & 7)) << 4));
                LDSM_X4(ph[0], ph[1], ph[2], ph[3], pd);
            }
#pragma unroll
            for (int pr = 0; pr < 8; ++pr) {
                int vk = ks * 16 + (lane & 15);
                int vc = pr * 2 + (lane >> 4);
                uint32_t vd = smem_u32(sm + A_VH + vk * 256 + ((vc ^ (vk & 7)) << 4));
                uint32_t b0, b1, b2, b3, c0, c1, c2, c3;
                LDSM_X4_T(b0, b1, b2, b3, vd);
                LDSM_X4_T(c0, c1, c2, c3, vd + (A_VL - A_VH));
                int nt0 = 2 * pr, nt1 = 2 * pr + 1;
                MMA16816(acc_o[nt0], ph[0], ph[1], ph[2], ph[3], c0, c1);
                MMA16816(acc_o[nt0], ph[0], ph[1], ph[2], ph[3], b0, b1);
                MMA16816(acc_o[nt1], ph[0], ph[1], ph[2], ph[3], c2, c3);
                MMA16816(acc_o[nt1], ph[0], ph[1], ph[2], ph[3], b2, b3);
            }
        }
        __syncthreads();
        if (more) fill_V(kb + 1);
        CP_COMMIT();
    }

    float inv0 = 1.f / l0;
    float inv1 = 1.f / l1;
#pragma unroll
    for (int nt = 0; nt < 16; ++nt) {
        int col = nt * 8 + 2 * t;
        *(__half2*)(ath + (size_t)(q0 + r0) * AW + hh_ * DV + col) =
            __float22half2_rn(make_float2(acc_o[nt][0] * inv0, acc_o[nt][1] * inv0));
        *(__half2*)(ath + (size_t)(q0 + r1) * AW + hh_ * DV + col) =
            __float22half2_rn(make_float2(acc_o[nt][2] * inv1, acc_o[nt][3] * inv1));
    }
}

// ---------------- launch ----------------
extern "C" void kernel_launch(void* const* d_in, const int* in_sizes, int n_in,
                              void* d_out, int out_size)
{
    const float* hidden = (const float*)d_in[0];
    const float* cosb   = (const float*)d_in[1];
    const float* sinb   = (const float*)d_in[2];
    const float* w_qa   = (const float*)d_in[3];
    const float* gm_qa  = (const float*)d_in[4];
    const float* w_qb   = (const float*)d_in[5];
    const float* w_kva  = (const float*)d_in[6];
    const float* gm_kva = (const float*)d_in[7];
    const float* w_kvb  = (const float*)d_in[8];
    const float* w_o    = (const float*)d_in[9];
    float* out = (float*)d_out;

    float *qc, *qf;
    __half *hidh, *wfh, *wfl, *qbh, *qbl, *kvbh, *kvbl, *oh, *ol;
    __half *qanh, *cknh, *qsh, *qsl, *kvh, *kvl, *kpeh, *kpel, *ath;
    cudaGetSymbolAddress((void**)&qc,   g_qc_s);
    cudaGetSymbolAddress((void**)&qf,   g_q_s);
    cudaGetSymbolAddress((void**)&hidh, g_hid_h);
    cudaGetSymbolAddress((void**)&wfh,  g_wf_h);  cudaGetSymbolAddress((void**)&wfl,  g_wf_l);
    cudaGetSymbolAddress((void**)&qbh,  g_qb_h);  cudaGetSymbolAddress((void**)&qbl,  g_qb_l);
    cudaGetSymbolAddress((void**)&kvbh, g_kvb_h); cudaGetSymbolAddress((void**)&kvbl, g_kvb_l);
    cudaGetSymbolAddress((void**)&oh,   g_o_h);   cudaGetSymbolAddress((void**)&ol,   g_o_l);
    cudaGetSymbolAddress((void**)&qanh, g_qan_h);
    cudaGetSymbolAddress((void**)&cknh, g_ckn_h);
    cudaGetSymbolAddress((void**)&qsh,  g_qs_h);  cudaGetSymbolAddress((void**)&qsl,  g_qs_l);
    cudaGetSymbolAddress((void**)&kvh,  g_kv_h);  cudaGetSymbolAddress((void**)&kvl,  g_kv_l);
    cudaGetSymbolAddress((void**)&kpeh, g_kpe_h); cudaGetSymbolAddress((void**)&kpel, g_kpe_l);
    cudaGetSymbolAddress((void**)&ath,  g_at_h);

    static bool attr_done = false;
    if (!attr_done) {
        cudaFuncSetAttribute(attn_mma, cudaFuncAttributeMaxDynamicSharedMemorySize,
                             ATTN_SMEM_BYTES);
        cudaFuncSetAttribute(gemm_f32out, cudaFuncAttributeMaxDynamicSharedMemorySize,
                             GEMM_SMEM_BYTES);
        cudaFuncSetAttribute(gemm_dual, cudaFuncAttributeMaxDynamicSharedMemorySize,
                             GEMM_SMEM_BYTES);
        attr_done = true;
    }

    prep_kernel<<<PREP_BLOCKS, 256>>>(hidden, w_qa, w_kva, w_qb, w_kvb, w_o,
                                      hidh, wfh, wfl, qbh, qbl, kvbh, kvbl, oh, ol);
    gemm_f32out<<<dim3(FWP / 128, SEQ / 128), 256, GEMM_SMEM_BYTES>>>(
        hidh, HID, wfh, wfl, FWP, qc, FWP, FW, HID);
    rmsnorm2_kernel<<<SEQ, 256>>>(qc, gm_qa, gm_kva, qanh, cknh);
    gemm_dual<<<G2_TILES + G3_TILES, 256, GEMM_SMEM_BYTES>>>(
        qanh, qbh, qbl, qf, cknh, kvbh, kvbl, kvh, kvl);
    rope_qsplit_kernel<<<SEQ + 256, 256>>>(qf, qc, qsh, qsl, kpeh, kpel, cosb, sinb);
    attn_mma<<<dim3(SEQ / 128, NH), 256, ATTN_SMEM_BYTES>>>(
        qsh, qsl, kvh, kvl, kpeh, kpel, ath);
    gemm_f32out<<<dim3(HID / 128, SEQ / 128), 256, GEMM_SMEM_BYTES>>>(
        ath, AW, oh, ol, HID, out, HID, HID, AW);
}

// round 15
// speedup vs baseline: 1.3309x; 1.2909x over previous
#include <cuda_runtime.h>
#include <cuda_fp16.h>
#include <cuda_bf16.h>
#include <stdint.h>
#include <math.h>

#define SEQ 2048
#define HID 2048
#define NH 16
#define QL 1536
#define KVL 512
#define DN 128
#define DR 64
#define DV 128
#define DQK 192
#define CKVW (KVL + DR)      // 576
#define FW (QL + CKVW)       // 2112
#define FWP 2176
#define QW (NH * DQK)        // 3072
#define KVW (NH * (DN + DV)) // 4096
#define AW (NH * DV)         // 2048

// ---------------- scratch ----------------
__device__ float  g_qc_s [(size_t)SEQ * FWP];
__device__ float  g_q_s  [(size_t)SEQ * QW];
__device__ __half g_hid_h[(size_t)SEQ * HID];
__device__ __half g_wf_h [(size_t)HID * FWP],  g_wf_l [(size_t)HID * FWP];
__device__ __half g_qb_h [(size_t)QL * QW],    g_qb_l [(size_t)QL * QW];
__device__ __half g_kvb_h[(size_t)KVL * KVW],  g_kvb_l[(size_t)KVL * KVW];
__device__ __half g_o_h  [(size_t)AW * HID],   g_o_l  [(size_t)AW * HID];
__device__ __half g_qan_h[(size_t)SEQ * QL];
__device__ __half g_ckn_h[(size_t)SEQ * KVL];
__device__ __half g_qs_h [(size_t)SEQ * QW],   g_qs_l [(size_t)SEQ * QW];
__device__ __half g_kv_h [(size_t)SEQ * KVW],  g_kv_l [(size_t)SEQ * KVW];
__device__ __half g_kpe_h[(size_t)SEQ * DR],   g_kpe_l[(size_t)SEQ * DR];
__device__ __half g_at_h [(size_t)SEQ * AW];

__device__ __forceinline__ uint32_t smem_u32(const void* p) {
    return (uint32_t)__cvta_generic_to_shared(p);
}

#define LDSM_X4(r0, r1, r2, r3, a)                                            \
    asm volatile("ldmatrix.sync.aligned.m8n8.x4.shared.b16 {%0,%1,%2,%3},[%4];" \
                 : "=r"(r0), "=r"(r1), "=r"(r2), "=r"(r3) : "r"(a))
#define LDSM_X4_T(r0, r1, r2, r3, a)                                          \
    asm volatile("ldmatrix.sync.aligned.m8n8.x4.trans.shared.b16 {%0,%1,%2,%3},[%4];" \
                 : "=r"(r0), "=r"(r1), "=r"(r2), "=r"(r3) : "r"(a))

#define MMA16816(d, a0, a1, a2, a3, b0, b1)                                   \
    asm volatile("mma.sync.aligned.m16n8k16.row.col.f32.f16.f16.f32 "         \
                 "{%0,%1,%2,%3},{%4,%5,%6,%7},{%8,%9},{%0,%1,%2,%3};"          \
                 : "+f"(d[0]), "+f"(d[1]), "+f"(d[2]), "+f"(d[3])              \
                 : "r"(a0), "r"(a1), "r"(a2), "r"(a3), "r"(b0), "r"(b1))

#define CP_ASYNC16(dst, src)                                                  \
    asm volatile("cp.async.cg.shared.global [%0], [%1], 16;" :: "r"(dst), "l"(src))
#define CP_COMMIT() asm volatile("cp.async.commit_group;" ::: "memory")
#define CP_WAIT1()  asm volatile("cp.async.wait_group 1;" ::: "memory")
#define CP_WAIT0()  asm volatile("cp.async.wait_group 0;" ::: "memory")

__device__ __forceinline__ void split_h2(float x, float y, uint32_t& h, uint32_t& l) {
    __half hx = __float2half_rn(x), hy = __float2half_rn(y);
    __half2 hp = __halves2half2(hx, hy);
    h = *(uint32_t*)&hp;
    __half2 lp = __halves2half2(__float2half_rn(x - __half2float(hx)),
                                __float2half_rn(y - __half2float(hy)));
    l = *(uint32_t*)&lp;
}

// ======== prep kernel, 4-way ILP ========
#define PNB1 2048
#define PNB2 2176
#define PNB3 2304
#define PNB4 1024
#define PNB5 2048
#define PREP_BLOCKS (PNB1 + PNB2 + PNB3 + PNB4 + PNB5)

__global__ __launch_bounds__(256) void prep_kernel(
    const float* __restrict__ hidden,
    const float* __restrict__ wqa, const float* __restrict__ wkva,
    const float* __restrict__ wqb, const float* __restrict__ wkvb,
    const float* __restrict__ wo,
    __half* __restrict__ hidh,
    __half* __restrict__ wfh, __half* __restrict__ wfl,
    __half* __restrict__ qbh, __half* __restrict__ qbl,
    __half* __restrict__ kvbh, __half* __restrict__ kvbl,
    __half* __restrict__ oh, __half* __restrict__ ol)
{
    int b = blockIdx.x;
    if (b < PNB1) {
        int i0 = b * 1024 + threadIdx.x;
        float2 v[4];
#pragma unroll
        for (int e = 0; e < 4; ++e) v[e] = ((const float2*)hidden)[i0 + e * 256];
#pragma unroll
        for (int e = 0; e < 4; ++e)
            ((__half2*)hidh)[i0 + e * 256] = __float22half2_rn(v[e]);
    } else if (b < PNB1 + PNB2) {
        int i0 = (b - PNB1) * 1024 + threadIdx.x;
        float2 v[4];
#pragma unroll
        for (int e = 0; e < 4; ++e) {
            int i = i0 + e * 256;
            int row = i / (FWP / 2), p = i % (FWP / 2);
            int col = 2 * p;
            float x = 0.f, y = 0.f;
            if (col < QL)      { x = wqa[(size_t)row * QL + col];         y = wqa[(size_t)row * QL + col + 1]; }
            else if (col < FW) { x = wkva[(size_t)row * CKVW + col - QL]; y = wkva[(size_t)row * CKVW + col - QL + 1]; }
            v[e] = make_float2(x, y);
        }
#pragma unroll
        for (int e = 0; e < 4; ++e) {
            uint32_t hh, ll;
            split_h2(v[e].x, v[e].y, hh, ll);
            ((uint32_t*)wfh)[i0 + e * 256] = hh;
            ((uint32_t*)wfl)[i0 + e * 256] = ll;
        }
    } else if (b < PNB1 + PNB2 + PNB3) {
        int i0 = (b - PNB1 - PNB2) * 1024 + threadIdx.x;
        float2 v[4];
#pragma unroll
        for (int e = 0; e < 4; ++e) v[e] = ((const float2*)wqb)[i0 + e * 256];
#pragma unroll
        for (int e = 0; e < 4; ++e) {
            uint32_t hh, ll;
            split_h2(v[e].x, v[e].y, hh, ll);
            ((uint32_t*)qbh)[i0 + e * 256] = hh;
            ((uint32_t*)qbl)[i0 + e * 256] = ll;
        }
    } else if (b < PNB1 + PNB2 + PNB3 + PNB4) {
        int i0 = (b - PNB1 - PNB2 - PNB3) * 1024 + threadIdx.x;
        float2 v[4];
#pragma unroll
        for (int e = 0; e < 4; ++e) v[e] = ((const float2*)wkvb)[i0 + e * 256];
#pragma unroll
        for (int e = 0; e < 4; ++e) {
            uint32_t hh, ll;
            split_h2(v[e].x, v[e].y, hh, ll);
            ((uint32_t*)kvbh)[i0 + e * 256] = hh;
            ((uint32_t*)kvbl)[i0 + e * 256] = ll;
        }
    } else {
        int i0 = (b - PNB1 - PNB2 - PNB3 - PNB4) * 1024 + threadIdx.x;
        float2 v[4];
#pragma unroll
        for (int e = 0; e < 4; ++e) v[e] = ((const float2*)wo)[i0 + e * 256];
#pragma unroll
        for (int e = 0; e < 4; ++e) {
            uint32_t hh, ll;
            split_h2(v[e].x, v[e].y, hh, ll);
            ((uint32_t*)oh)[i0 + e * 256] = hh;
            ((uint32_t*)ol)[i0 + e * 256] = ll;
        }
    }
}

// ---------------- both RMSNorms ----------------
__global__ __launch_bounds__(256) void rmsnorm2_kernel(
    const float* __restrict__ qc, const float* __restrict__ gqa,
    const float* __restrict__ gkva, __half* __restrict__ qanh,
    __half* __restrict__ cknh)
{
    __shared__ float red[256];
    const float* p = qc + (size_t)blockIdx.x * FWP;
    float s = 0.f;
    for (int i = threadIdx.x; i < QL; i += 256) { float v = p[i]; s += v * v; }
    red[threadIdx.x] = s;
    __syncthreads();
#pragma unroll
    for (int off = 128; off > 0; off >>= 1) {
        if (threadIdx.x < off) red[threadIdx.x] += red[threadIdx.x + off];
        __syncthreads();
    }
    float inv = rsqrtf(red[0] / (float)QL + 1e-6f);
    for (int i = threadIdx.x; i < QL / 2; i += 256) {
        float v0 = p[2 * i] * inv * gqa[2 * i];
        float v1 = p[2 * i + 1] * inv * gqa[2 * i + 1];
        ((__half2*)qanh)[(size_t)blockIdx.x * (QL / 2) + i] = __float22half2_rn(make_float2(v0, v1));
    }
    __syncthreads();
    const float* p2 = p + QL;
    s = 0.f;
    for (int i = threadIdx.x; i < KVL; i += 256) { float v = p2[i]; s += v * v; }
    red[threadIdx.x] = s;
    __syncthreads();
#pragma unroll
    for (int off = 128; off > 0; off >>= 1) {
        if (threadIdx.x < off) red[threadIdx.x] += red[threadIdx.x + off];
        __syncthreads();
    }
    inv = rsqrtf(red[0] / (float)KVL + 1e-6f);
    for (int i = threadIdx.x; i < KVL / 2; i += 256) {
        float v0 = p2[2 * i] * inv * gkva[2 * i];
        float v1 = p2[2 * i + 1] * inv * gkva[2 * i + 1];
        ((__half2*)cknh)[(size_t)blockIdx.x * (KVL / 2) + i] = __float22half2_rn(make_float2(v0, v1));
    }
}

// ======== fp16x2 GEMM core (2-stage K64 ring, 2 CTAs/SM) ========
#define G_AT 16384
#define G_BT 16384
#define G_STAGE (G_AT + 2 * G_BT)
#define GEMM_SMEM_BYTES (2 * G_STAGE)

__device__ __forceinline__ void gemm_core(
    const __half* __restrict__ Ah, int lda,
    const __half* __restrict__ Bh, const __half* __restrict__ Bl, int ldb,
    float* __restrict__ C, __half* __restrict__ Ch, __half* __restrict__ Cl,
    int ldc, int N, int K, int row0, int col0, bool split_out, char* sm)
{
    const uint32_t sbase = smem_u32(sm);
    const int tid  = threadIdx.x;
    const int lane = tid & 31, w = tid >> 5;
    const int wm = w & 3, wn = w >> 2;

    float acc[2][8][4];
#pragma unroll
    for (int mt = 0; mt < 2; ++mt)
#pragma unroll
        for (int nt = 0; nt < 8; ++nt)
#pragma unroll
            for (int i = 0; i < 4; ++i) acc[mt][nt][i] = 0.f;

    auto do_cp = [&](int stage, int k0) {
        uint32_t sb = sbase + stage * G_STAGE;
#pragma unroll
        for (int i = 0; i < 4; ++i) {
            int idx = i * 256 + tid;
            int r = idx >> 3, u = idx & 7;
            uint32_t off = r * 128 + ((u ^ (r & 7)) << 4);
            CP_ASYNC16(sb + off, Ah + (size_t)(row0 + r) * lda + k0 + u * 8);
        }
#pragma unroll
        for (int i = 0; i < 4; ++i) {
            int idx = i * 256 + tid;
            int r = idx >> 4, u = idx & 15;
            uint32_t off = G_AT + r * 256 + ((u ^ (r & 7)) << 4);
            CP_ASYNC16(sb + off, Bh + (size_t)(k0 + r) * ldb + col0 + u * 8);
            CP_ASYNC16(sb + G_BT + off, Bl + (size_t)(k0 + r) * ldb + col0 + u * 8);
        }
    };

    const int nIter = K >> 6;
    do_cp(0, 0);
    CP_COMMIT();
    if (nIter > 1) do_cp(1, 64);
    CP_COMMIT();

    for (int it = 0; it < nIter; ++it) {
        CP_WAIT1();
        __syncthreads();

        char* base = sm + (it & 1) * G_STAGE;
#pragma unroll
        for (int kg = 0; kg < 4; ++kg) {
            uint32_t ah[2][4];
#pragma unroll
            for (int mt = 0; mt < 2; ++mt) {
                int row = wm * 32 + mt * 16 + (lane & 15);
                int kc = kg * 2 + (lane >> 4);
                uint32_t ad = smem_u32(base + row * 128 + ((kc ^ (row & 7)) << 4));
                LDSM_X4(ah[mt][0], ah[mt][1], ah[mt][2], ah[mt][3], ad);
            }
            uint32_t bh[8][2], bl[8][2];
#pragma unroll
            for (int pr = 0; pr < 4; ++pr) {
                int k = kg * 16 + (lane & 15);
                int nc = wn * 8 + pr * 2 + (lane >> 4);
                uint32_t bd = smem_u32(base + G_AT + k * 256 + ((nc ^ (k & 7)) << 4));
                uint32_t t0, t1, t2, t3;
                LDSM_X4_T(t0, t1, t2, t3, bd);
                bh[2 * pr][0] = t0; bh[2 * pr][1] = t1;
                bh[2 * pr + 1][0] = t2; bh[2 * pr + 1][1] = t3;
                LDSM_X4_T(t0, t1, t2, t3, bd + G_BT);
                bl[2 * pr][0] = t0; bl[2 * pr][1] = t1;
                bl[2 * pr + 1][0] = t2; bl[2 * pr + 1][1] = t3;
            }
#pragma unroll
            for (int mt = 0; mt < 2; ++mt)
#pragma unroll
                for (int nt = 0; nt < 8; ++nt) {
                    MMA16816(acc[mt][nt], ah[mt][0], ah[mt][1], ah[mt][2], ah[mt][3],
                             bl[nt][0], bl[nt][1]);
                    MMA16816(acc[mt][nt], ah[mt][0], ah[mt][1], ah[mt][2], ah[mt][3],
                             bh[nt][0], bh[nt][1]);
                }
        }
        __syncthreads();
        if (it + 2 < nIter) {
            do_cp(it & 1, (it + 2) << 6);
            CP_COMMIT();
        }
    }

    const int g = lane >> 2, t = lane & 3;
#pragma unroll
    for (int mt = 0; mt < 2; ++mt) {
        int r = row0 + wm * 32 + mt * 16 + g;
#pragma unroll
        for (int nt = 0; nt < 8; ++nt) {
            int c = col0 + wn * 64 + nt * 8 + 2 * t;
            if (split_out) {
                uint32_t hh, ll;
                split_h2(acc[mt][nt][0], acc[mt][nt][1], hh, ll);
                *(uint32_t*)(Ch + (size_t)r * ldc + c) = hh;
                *(uint32_t*)(Cl + (size_t)r * ldc + c) = ll;
                split_h2(acc[mt][nt][2], acc[mt][nt][3], hh, ll);
                *(uint32_t*)(Ch + (size_t)(r + 8) * ldc + c) = hh;
                *(uint32_t*)(Cl + (size_t)(r + 8) * ldc + c) = ll;
            } else if (c < N) {
                *(float2*)(C + (size_t)r * ldc + c)       = make_float2(acc[mt][nt][0], acc[mt][nt][1]);
                *(float2*)(C + (size_t)(r + 8) * ldc + c) = make_float2(acc[mt][nt][2], acc[mt][nt][3]);
            }
        }
    }
}

__global__ __launch_bounds__(256, 2) void gemm_f32out(
    const __half* __restrict__ Ah, int lda,
    const __half* __restrict__ Bh, const __half* __restrict__ Bl, int ldb,
    float* __restrict__ C, int ldc, int N, int K)
{
    extern __shared__ char sm[];
    gemm_core(Ah, lda, Bh, Bl, ldb, C, (__half*)0, (__half*)0, ldc, N, K,
              blockIdx.y * 128, blockIdx.x * 128, false, sm);
}

#define G2_TILES 384
#define G3_TILES 512
__global__ __launch_bounds__(256, 2) void gemm_dual(
    const __half* __restrict__ A2, const __half* __restrict__ B2h,
    const __half* __restrict__ B2l, float* __restrict__ C2,
    const __half* __restrict__ A3, const __half* __restrict__ B3h,
    const __half* __restrict__ B3l, __half* __restrict__ C3h, __half* __restrict__ C3l)
{
    extern __shared__ char sm[];
    int b = blockIdx.x;
    if (b < G2_TILES) {
        gemm_core(A2, QL, B2h, B2l, QW, C2, (__half*)0, (__half*)0, QW, QW, QL,
                  (b / 24) * 128, (b % 24) * 128, false, sm);
    } else {
        int r = b - G2_TILES;
        gemm_core(A3, KVL, B3h, B3l, KVW, (float*)0, C3h, C3l, KVW, KVW, KVL,
                  (r / 32) * 128, (r % 32) * 128, true, sm);
    }
}

// ------- RoPE on q + full q split; kpe in tail blocks -------
__global__ __launch_bounds__(256) void rope_qsplit_kernel(
    const float* __restrict__ qf, const float* __restrict__ qc,
    __half* __restrict__ qsh, __half* __restrict__ qsl,
    __half* __restrict__ kpeh, __half* __restrict__ kpel,
    const float* __restrict__ cosb, const float* __restrict__ sinb)
{
    __shared__ float row[QW];
    int b = blockIdx.x;
    if (b < SEQ) {
        const int s = b;
        const float* src = qf + (size_t)s * QW;
#pragma unroll
        for (int i = 0; i < 3; ++i) {
            int idx = (i * 256 + threadIdx.x) * 4;
            *(float4*)(row + idx) = *(const float4*)(src + idx);
        }
        __syncthreads();
        float y0[2], y1[2];
        int hd[2], ln[2];
#pragma unroll
        for (int e = 0; e < 2; ++e) {
            int item = threadIdx.x + e * 256;
            hd[e] = item >> 5; ln[e] = item & 31;
            float c  = cosb[s * DR + ln[e]];
            float sn = sinb[s * DR + ln[e]];
            float x0 = row[hd[e] * DQK + DN + 2 * ln[e]];
            float x1 = row[hd[e] * DQK + DN + 2 * ln[e] + 1];
            y0[e] = x0 * c - x1 * sn;
            y1[e] = x1 * c + x0 * sn;
        }
        __syncthreads();
#pragma unroll
        for (int e = 0; e < 2; ++e) {
            row[hd[e] * DQK + DN + ln[e]]      = y0[e];
            row[hd[e] * DQK + DN + ln[e] + 32] = y1[e];
        }
        __syncthreads();
#pragma unroll
        for (int i = 0; i < 6; ++i) {
            int p = i * 256 + threadIdx.x;
            uint32_t hh, ll;
            split_h2(row[2 * p], row[2 * p + 1], hh, ll);
            ((uint32_t*)qsh)[(size_t)s * (QW / 2) + p] = hh;
            ((uint32_t*)qsl)[(size_t)s * (QW / 2) + p] = ll;
        }
    } else {
        int wr = (b - SEQ) * 8 + (threadIdx.x >> 5);
        int lane = threadIdx.x & 31;
        const float* x = qc + (size_t)wr * FWP + QL + KVL;
        float c  = cosb[wr * DR + lane];
        float sn = sinb[wr * DR + lane];
        float x0 = x[2 * lane], x1 = x[2 * lane + 1];
        float z0 = x0 * c - x1 * sn;
        float z1 = x1 * c + x0 * sn;
        __half h0 = __float2half_rn(z0);
        __half h1 = __float2half_rn(z1);
        kpeh[wr * DR + lane]      = h0;
        kpel[wr * DR + lane]      = __float2half_rn(z0 - __half2float(h0));
        kpeh[wr * DR + lane + 32] = h1;
        kpel[wr * DR + lane + 32] = __float2half_rn(z1 - __half2float(h1));
    }
}

// ==== flash attention BQ=128/BK=64: global descending-work CTA order ====
#define A_QH 0
#define A_QL 49152
#define A_KH 98304
#define A_KL 122880
#define A_VH 147456
#define A_VL 163840
#define A_PH 180224
#define ATTN_SMEM_BYTES 196608

__global__ __launch_bounds__(256) void attn_mma(
    const __half* __restrict__ qh, const __half* __restrict__ ql,
    const __half* __restrict__ kvh, const __half* __restrict__ kvl,
    const __half* __restrict__ kpeh, const __half* __restrict__ kpel,
    __half* __restrict__ ath)
{
    extern __shared__ char sm[];
    const uint32_t sb = smem_u32(sm);

    const int tid = threadIdx.x, lane = tid & 31, wm = tid >> 5;
    // global descending work order: heaviest q-blocks (highest qb) first, all heads
    const int qb  = (SEQ / 128 - 1) - (blockIdx.x >> 4);
    const int hh_ = blockIdx.x & 15;
    const int q0 = qb * 128;
    const float scale = rsqrtf((float)DQK);
    const int nkb = 2 * qb + 2;

    auto fill_K = [&](int kb) {
        const int k0 = kb * 64;
#pragma unroll
        for (int i = 0; i < 6; ++i) {
            int idx = i * 256 + tid;
            int r = idx / 24, u = idx % 24;
            uint32_t off = r * 384 + ((u ^ (r & 7)) << 4);
            if (u < 16) {
                const size_t go = (size_t)(k0 + r) * KVW + hh_ * (DN + DV) + u * 8;
                CP_ASYNC16(sb + A_KH + off, kvh + go);
                CP_ASYNC16(sb + A_KL + off, kvl + go);
            } else {
                const size_t go = (size_t)(k0 + r) * DR + (u - 16) * 8;
                CP_ASYNC16(sb + A_KH + off, kpeh + go);
                CP_ASYNC16(sb + A_KL + off, kpel + go);
            }
        }
    };
    auto fill_V = [&](int kb) {
        const int k0 = kb * 64;
#pragma unroll
        for (int i = 0; i < 4; ++i) {
            int idx = i * 256 + tid;
            int r = idx >> 4, u = idx & 15;
            uint32_t off = r * 256 + ((u ^ (r & 7)) << 4);
            const size_t go = (size_t)(k0 + r) * KVW + hh_ * (DN + DV) + DN + u * 8;
            CP_ASYNC16(sb + A_VH + off, kvh + go);
            CP_ASYNC16(sb + A_VL + off, kvl + go);
        }
    };

    fill_K(0); CP_COMMIT();
    fill_V(0); CP_COMMIT();
#pragma unroll
    for (int i = 0; i < 12; ++i) {
        int idx = i * 256 + tid;
        int r = idx / 24, u = idx % 24;
        int off = r * 384 + ((u ^ (r & 7)) << 4);
        const size_t go = (size_t)(q0 + r) * QW + hh_ * DQK + u * 8;
        *(uint4*)(sm + A_QH + off) = *(const uint4*)(qh + go);
        *(uint4*)(sm + A_QL + off) = *(const uint4*)(ql + go);
    }

    const int g = lane >> 2, t = lane & 3;
    const int r0 = wm * 16 + g, r1 = r0 + 8;

    float m0 = -1e30f, m1 = -1e30f, l0 = 0.f, l1 = 0.f;
    float acc_o[16][4];
#pragma unroll
    for (int nt = 0; nt < 16; ++nt)
#pragma unroll
        for (int i = 0; i < 4; ++i) acc_o[nt][i] = 0.f;

    for (int kb = 0; kb < nkb; ++kb) {
        const int k0 = kb * 64;
        const bool more = (kb + 1 < nkb);

        CP_WAIT1();
        __syncthreads();

        float acc_s[8][4];
#pragma unroll
        for (int nt = 0; nt < 8; ++nt)
#pragma unroll
            for (int i = 0; i < 4; ++i) acc_s[nt][i] = 0.f;

#pragma unroll
        for (int ks = 0; ks < 12; ++ks) {
            uint32_t qfh[4], qfl[4];
            {
                int rowi = wm * 16 + (lane & 15);
                int c = 2 * ks + (lane >> 4);
                uint32_t ad = smem_u32(sm + rowi * 384 + ((c ^ (rowi & 7)) << 4));
                LDSM_X4(qfh[0], qfh[1], qfh[2], qfh[3], ad + A_QH);
                LDSM_X4(qfl[0], qfl[1], qfl[2], qfl[3], ad + (A_QL - A_QH));
            }
            // K frags: one LDSM_X4 covers an nt-pair (rows pr*16..+15, kc/kc+1)
#pragma unroll
            for (int pr = 0; pr < 4; ++pr) {
                int krow = pr * 16 + ((lane >> 4) << 3) + (lane & 7);
                int kc = 2 * ks + ((lane >> 3) & 1);
                uint32_t kd = smem_u32(sm + A_KH + krow * 384 + ((kc ^ (krow & 7)) << 4));
                uint32_t h0, h1, h2, h3, l0r, l1r, l2r, l3r;
                LDSM_X4(h0, h1, h2, h3, kd);
                LDSM_X4(l0r, l1r, l2r, l3r, kd + (A_KL - A_KH));
                int n0 = 2 * pr, n1 = 2 * pr + 1;
                MMA16816(acc_s[n0], qfh[0], qfh[1], qfh[2], qfh[3], l0r, l1r);
                MMA16816(acc_s[n0], qfl[0], qfl[1], qfl[2], qfl[3], h0, h1);
                MMA16816(acc_s[n0], qfh[0], qfh[1], qfh[2], qfh[3], h0, h1);
                MMA16816(acc_s[n1], qfh[0], qfh[1], qfh[2], qfh[3], l2r, l3r);
                MMA16816(acc_s[n1], qfl[0], qfl[1], qfl[2], qfl[3], h2, h3);
                MMA16816(acc_s[n1], qfh[0], qfh[1], qfh[2], qfh[3], h2, h3);
            }
        }
        __syncthreads();
        if (more) fill_K(kb + 1);
        CP_COMMIT();

        float vm0 = -1e30f, vm1 = -1e30f;
#pragma unroll
        for (int nt = 0; nt < 8; ++nt) {
            int col = k0 + nt * 8 + 2 * t;
            float v00 = acc_s[nt][0] * scale, v01 = acc_s[nt][1] * scale;
            float v10 = acc_s[nt][2] * scale, v11 = acc_s[nt][3] * scale;
            if (col     > q0 + r0) v00 = -1e30f;
            if (col + 1 > q0 + r0) v01 = -1e30f;
            if (col     > q0 + r1) v10 = -1e30f;
            if (col + 1 > q0 + r1) v11 = -1e30f;
            acc_s[nt][0] = v00; acc_s[nt][1] = v01;
            acc_s[nt][2] = v10; acc_s[nt][3] = v11;
            vm0 = fmaxf(vm0, fmaxf(v00, v01));
            vm1 = fmaxf(vm1, fmaxf(v10, v11));
        }
        vm0 = fmaxf(vm0, __shfl_xor_sync(0xffffffffu, vm0, 1));
        vm0 = fmaxf(vm0, __shfl_xor_sync(0xffffffffu, vm0, 2));
        vm1 = fmaxf(vm1, __shfl_xor_sync(0xffffffffu, vm1, 1));
        vm1 = fmaxf(vm1, __shfl_xor_sync(0xffffffffu, vm1, 2));

        float mnew0 = fmaxf(m0, vm0);
        float mnew1 = fmaxf(m1, vm1);
        float alpha0 = __expf(m0 - mnew0);
        float alpha1 = __expf(m1 - mnew1);
        m0 = mnew0; m1 = mnew1;

        float s0 = 0.f, s1 = 0.f;
#pragma unroll
        for (int nt = 0; nt < 8; ++nt) {
            float p00 = __expf(acc_s[nt][0] - mnew0);
            float p01 = __expf(acc_s[nt][1] - mnew0);
            float p10 = __expf(acc_s[nt][2] - mnew1);
            float p11 = __expf(acc_s[nt][3] - mnew1);
            s0 += p00 + p01;
            s1 += p10 + p11;
            int off0 = r0 * 128 + ((nt ^ (r0 & 7)) << 4) + t * 4;
            *(__half2*)(sm + A_PH + off0) = __float22half2_rn(make_float2(p00, p01));
            int off1 = r1 * 128 + ((nt ^ (r1 & 7)) << 4) + t * 4;
            *(__half2*)(sm + A_PH + off1) = __float22half2_rn(make_float2(p10, p11));
        }
        s0 += __shfl_xor_sync(0xffffffffu, s0, 1);
        s0 += __shfl_xor_sync(0xffffffffu, s0, 2);
        s1 += __shfl_xor_sync(0xffffffffu, s1, 1);
        s1 += __shfl_xor_sync(0xffffffffu, s1, 2);
        l0 = l0 * alpha0 + s0;
        l1 = l1 * alpha1 + s1;
        __syncwarp();

        if (more) { CP_WAIT1(); } else { CP_WAIT0(); }
        __syncthreads();

#pragma unroll
        for (int nt = 0; nt < 16; ++nt) {
            acc_o[nt][0] *= alpha0; acc_o[nt][1] *= alpha0;
            acc_o[nt][2] *= alpha1; acc_o[nt][3] *= alpha1;
        }
#pragma unroll
        for (int ks = 0; ks < 4; ++ks) {
            uint32_t ph[4];
            {
                int rowi = wm * 16 + (lane & 15);
                int c = 2 * ks + (lane >> 4);
                uint32_t pd = smem_u32(sm + A_PH + rowi * 128 + ((c ^ (rowi & 7)) << 4));
                LDSM_X4(ph[0], ph[1], ph[2], ph[3], pd);
            }
#pragma unroll
            for (int pr = 0; pr < 8; ++pr) {
                int vk = ks * 16 + (lane & 15);
                int vc = pr * 2 + (lane >> 4);
                uint32_t vd = smem_u32(sm + A_VH + vk * 256 + ((vc ^ (vk & 7)) << 4));
                uint32_t b0, b1, b2, b3, c0, c1, c2, c3;
                LDSM_X4_T(b0, b1, b2, b3, vd);
                LDSM_X4_T(c0, c1, c2, c3, vd + (A_VL - A_VH));
                int nt0 = 2 * pr, nt1 = 2 * pr + 1;
                MMA16816(acc_o[nt0], ph[0], ph[1], ph[2], ph[3], c0, c1);
                MMA16816(acc_o[nt0], ph[0], ph[1], ph[2], ph[3], b0, b1);
                MMA16816(acc_o[nt1], ph[0], ph[1], ph[2], ph[3], c2, c3);
                MMA16816(acc_o[nt1], ph[0], ph[1], ph[2], ph[3], b2, b3);
            }
        }
        __syncthreads();
        if (more) fill_V(kb + 1);
        CP_COMMIT();
    }

    float inv0 = 1.f / l0;
    float inv1 = 1.f / l1;
#pragma unroll
    for (int nt = 0; nt < 16; ++nt) {
        int col = nt * 8 + 2 * t;
        *(__half2*)(ath + (size_t)(q0 + r0) * AW + hh_ * DV + col) =
            __float22half2_rn(make_float2(acc_o[nt][0] * inv0, acc_o[nt][1] * inv0));
        *(__half2*)(ath + (size_t)(q0 + r1) * AW + hh_ * DV + col) =
            __float22half2_rn(make_float2(acc_o[nt][2] * inv1, acc_o[nt][3] * inv1));
    }
}

// ---------------- launch ----------------
extern "C" void kernel_launch(void* const* d_in, const int* in_sizes, int n_in,
                              void* d_out, int out_size)
{
    const float* hidden = (const float*)d_in[0];
    const float* cosb   = (const float*)d_in[1];
    const float* sinb   = (const float*)d_in[2];
    const float* w_qa   = (const float*)d_in[3];
    const float* gm_qa  = (const float*)d_in[4];
    const float* w_qb   = (const float*)d_in[5];
    const float* w_kva  = (const float*)d_in[6];
    const float* gm_kva = (const float*)d_in[7];
    const float* w_kvb  = (const float*)d_in[8];
    const float* w_o    = (const float*)d_in[9];
    float* out = (float*)d_out;

    float *qc, *qf;
    __half *hidh, *wfh, *wfl, *qbh, *qbl, *kvbh, *kvbl, *oh, *ol;
    __half *qanh, *cknh, *qsh, *qsl, *kvh, *kvl, *kpeh, *kpel, *ath;
    cudaGetSymbolAddress((void**)&qc,   g_qc_s);
    cudaGetSymbolAddress((void**)&qf,   g_q_s);
    cudaGetSymbolAddress((void**)&hidh, g_hid_h);
    cudaGetSymbolAddress((void**)&wfh,  g_wf_h);  cudaGetSymbolAddress((void**)&wfl,  g_wf_l);
    cudaGetSymbolAddress((void**)&qbh,  g_qb_h);  cudaGetSymbolAddress((void**)&qbl,  g_qb_l);
    cudaGetSymbolAddress((void**)&kvbh, g_kvb_h); cudaGetSymbolAddress((void**)&kvbl, g_kvb_l);
    cudaGetSymbolAddress((void**)&oh,   g_o_h);   cudaGetSymbolAddress((void**)&ol,   g_o_l);
    cudaGetSymbolAddress((void**)&qanh, g_qan_h);
    cudaGetSymbolAddress((void**)&cknh, g_ckn_h);
    cudaGetSymbolAddress((void**)&qsh,  g_qs_h);  cudaGetSymbolAddress((void**)&qsl,  g_qs_l);
    cudaGetSymbolAddress((void**)&kvh,  g_kv_h);  cudaGetSymbolAddress((void**)&kvl,  g_kv_l);
    cudaGetSymbolAddress((void**)&kpeh, g_kpe_h); cudaGetSymbolAddress((void**)&kpel, g_kpe_l);
    cudaGetSymbolAddress((void**)&ath,  g_at_h);

    static bool attr_done = false;
    if (!attr_done) {
        cudaFuncSetAttribute(attn_mma, cudaFuncAttributeMaxDynamicSharedMemorySize,
                             ATTN_SMEM_BYTES);
        cudaFuncSetAttribute(gemm_f32out, cudaFuncAttributeMaxDynamicSharedMemorySize,
                             GEMM_SMEM_BYTES);
        cudaFuncSetAttribute(gemm_dual, cudaFuncAttributeMaxDynamicSharedMemorySize,
                             GEMM_SMEM_BYTES);
        attr_done = true;
    }

    prep_kernel<<<PREP_BLOCKS, 256>>>(hidden, w_qa, w_kva, w_qb, w_kvb, w_o,
                                      hidh, wfh, wfl, qbh, qbl, kvbh, kvbl, oh, ol);
    gemm_f32out<<<dim3(FWP / 128, SEQ / 128), 256, GEMM_SMEM_BYTES>>>(
        hidh, HID, wfh, wfl, FWP, qc, FWP, FW, HID);
    rmsnorm2_kernel<<<SEQ, 256>>>(qc, gm_qa, gm_kva, qanh, cknh);
    gemm_dual<<<G2_TILES + G3_TILES, 256, GEMM_SMEM_BYTES>>>(
        qanh, qbh, qbl, qf, cknh, kvbh, kvbl, kvh, kvl);
    rope_qsplit_kernel<<<SEQ + 256, 256>>>(qf, qc, qsh, qsl, kpeh, kpel, cosb, sinb);
    attn_mma<<<(SEQ / 128) * NH, 256, ATTN_SMEM_BYTES>>>(
        qsh, qsl, kvh, kvl, kpeh, kpel, ath);
    gemm_f32out<<<dim3(HID / 128, SEQ / 128), 256, GEMM_SMEM_BYTES>>>(
        ath, AW, oh, ol, HID, out, HID, HID, AW);
}